// round 2
// baseline (speedup 1.0000x reference)
#include <cuda_runtime.h>

// ---------------------------------------------------------------------------
// SwitchFeedForward (top-1 MoE FFN), T=8192 tokens, d_model=1024, d_ff=4096, E=8
//
// Pipeline (all graph-capturable, allocation-free):
//   init      : zero per-expert counters
//   router    : logits -> softmax -> argmax/pmax/probs/counts
//   finalize  : deterministic prob sums, counts->out, expert offsets, tile table
//   scatter   : counting-sort token ids into per-expert contiguous perm[]
//   gemm1     : H[rows,f] = relu( X[perm] @ w1[e]^T + b1[e] )   (grouped)
//   gemm2     : out[tok,m] = H @ w2[e]^T + b2[e]                 (grouped, scatter)
//
// Output layout (float32): final[8388608] | counts[8] | prob_sum[8] | 0 | pmax[8192]
// ---------------------------------------------------------------------------

#define T_TOK   8192
#define DM      1024
#define DF      4096
#define NE      8

#define OFF_FINAL 0
#define OFF_CNT   (T_TOK * DM)          // 8388608
#define OFF_PSUM  (OFF_CNT + NE)        // 8388616
#define OFF_ZERO  (OFF_PSUM + NE)       // 8388624
#define OFF_PMAX  (OFF_ZERO + 1)        // 8388625

#define BM 128
#define BN 128
#define BK 8
#define MAX_SLOTS 80   // worst case sum(ceil(cnt_e/128)) <= 71

// ----------------------------- device scratch ------------------------------
__device__ float g_H[(size_t)T_TOK * DF];     // 134 MB intermediate activations
__device__ float g_probs[T_TOK * NE];
__device__ int   g_routes[T_TOK];
__device__ int   g_cnt[NE];
__device__ int   g_off[NE];
__device__ int   g_fill[NE];
__device__ int   g_perm[T_TOK];
__device__ int   g_slot_e[MAX_SLOTS];
__device__ int   g_slot_row0[MAX_SLOTS];
__device__ int   g_slot_nv[MAX_SLOTS];
__device__ int   g_nslots;

// ------------------------------- kernels -----------------------------------

__global__ void init_kernel() {
    if (threadIdx.x < NE) g_cnt[threadIdx.x] = 0;
}

// One warp per token: 8 dot products of length 1024, then softmax on lane 0.
__global__ void router_kernel(const float* __restrict__ x,
                              const float* __restrict__ sw,
                              const float* __restrict__ sb,
                              float* __restrict__ out_pmax) {
    int warp = threadIdx.x >> 5;
    int lane = threadIdx.x & 31;
    int t = blockIdx.x * 8 + warp;
    if (t >= T_TOK) return;

    const float* xp = x + (size_t)t * DM;
    float acc[NE];
#pragma unroll
    for (int e = 0; e < NE; e++) acc[e] = 0.f;

#pragma unroll 4
    for (int j = 0; j < DM / 32; j++) {
        int idx = lane + 32 * j;
        float xv = xp[idx];
#pragma unroll
        for (int e = 0; e < NE; e++) acc[e] += xv * sw[e * DM + idx];
    }
#pragma unroll
    for (int o = 16; o > 0; o >>= 1) {
#pragma unroll
        for (int e = 0; e < NE; e++)
            acc[e] += __shfl_xor_sync(0xffffffffu, acc[e], o);
    }

    if (lane == 0) {
        float l[NE];
        float m = -1e30f;
#pragma unroll
        for (int e = 0; e < NE; e++) { l[e] = acc[e] + sb[e]; m = fmaxf(m, l[e]); }
        float p[NE];
        float s = 0.f;
#pragma unroll
        for (int e = 0; e < NE; e++) { p[e] = expf(l[e] - m); s += p[e]; }
        float inv = 1.f / s;
        int best = 0;
        float bp = p[0];
#pragma unroll
        for (int e = 1; e < NE; e++) if (p[e] > bp) { bp = p[e]; best = e; }
#pragma unroll
        for (int e = 0; e < NE; e++) g_probs[t * NE + e] = p[e] * inv;
        out_pmax[t] = bp * inv;
        g_routes[t] = best;
        atomicAdd(&g_cnt[best], 1);
    }
}

// One block: deterministic prob sums (warp e handles expert e in fixed lane
// order), counts -> out, exclusive offsets, tile (slot) table, zero scalar.
__global__ void finalize_kernel(float* __restrict__ out) {
    int tid = threadIdx.x, warp = tid >> 5, lane = tid & 31;
    if (warp < NE) {
        float sum = 0.f;
        for (int t = lane; t < T_TOK; t += 32) sum += g_probs[t * NE + warp];
#pragma unroll
        for (int o = 16; o > 0; o >>= 1) sum += __shfl_xor_sync(0xffffffffu, sum, o);
        if (lane == 0) out[OFF_PSUM + warp] = sum;
    }
    if (tid == 0) {
        int off = 0, ns = 0;
        for (int e = 0; e < NE; e++) {
            int c = g_cnt[e];
            g_off[e] = off;
            g_fill[e] = 0;
            out[OFF_CNT + e] = (float)c;
            for (int i = 0; i < c; i += BM) {
                g_slot_e[ns] = e;
                g_slot_row0[ns] = off + i;
                g_slot_nv[ns] = min(BM, c - i);
                ns++;
            }
            off += c;
        }
        g_nslots = ns;
        out[OFF_ZERO] = 0.f;
    }
}

__global__ void scatter_kernel() {
    int t = blockIdx.x * blockDim.x + threadIdx.x;
    if (t < T_TOK) {
        int e = g_routes[t];
        int pos = g_off[e] + atomicAdd(&g_fill[e], 1);
        g_perm[pos] = t;
    }
}

// -------- GEMM1: H[row, f] = relu( X[perm[row], :] @ w1[e][f, :] + b1[e][f] )
// 128x128x8 tile, 8x8 microtile, 256 threads, reg-prefetch single smem buffer.
__global__ __launch_bounds__(256, 2)
void gemm1_kernel(const float* __restrict__ x,
                  const float* __restrict__ w1,
                  const float* __restrict__ b1) {
    int slot = blockIdx.y;
    if (slot >= g_nslots) return;
    int e    = g_slot_e[slot];
    int row0 = g_slot_row0[slot];
    int nv   = g_slot_nv[slot];
    const float* Bp = w1 + (size_t)e * DF * DM;
    int nb = blockIdx.x * BN;

    __shared__ float As[BK][BM + 4];
    __shared__ float Bs[BK][BN + 4];
    __shared__ int   toks[BM];

    int tid = threadIdx.x;
    if (tid < BM) toks[tid] = g_perm[row0 + min(tid, nv - 1)];
    __syncthreads();

    int arow = tid >> 1;
    int ak   = (tid & 1) * 4;
    const float* Arowp = x + (size_t)toks[arow] * DM + ak;
    const float* Browp = Bp + (size_t)(nb + arow) * DM + ak;

    int tx = tid & 15, ty = tid >> 4;

    float acc[8][8];
#pragma unroll
    for (int i = 0; i < 8; i++)
#pragma unroll
        for (int j = 0; j < 8; j++) acc[i][j] = 0.f;

    float4 a_reg = *(const float4*)(Arowp);
    float4 b_reg = *(const float4*)(Browp);

    for (int k0 = 0; k0 < DM; k0 += BK) {
        As[ak + 0][arow] = a_reg.x; As[ak + 1][arow] = a_reg.y;
        As[ak + 2][arow] = a_reg.z; As[ak + 3][arow] = a_reg.w;
        Bs[ak + 0][arow] = b_reg.x; Bs[ak + 1][arow] = b_reg.y;
        Bs[ak + 2][arow] = b_reg.z; Bs[ak + 3][arow] = b_reg.w;
        __syncthreads();
        if (k0 + BK < DM) {
            a_reg = *(const float4*)(Arowp + k0 + BK);
            b_reg = *(const float4*)(Browp + k0 + BK);
        }
#pragma unroll
        for (int k = 0; k < BK; k++) {
            float ra[8], rb[8];
#pragma unroll
            for (int i = 0; i < 8; i++) ra[i] = As[k][ty * 8 + i];
#pragma unroll
            for (int j = 0; j < 8; j++) rb[j] = Bs[k][tx * 8 + j];
#pragma unroll
            for (int i = 0; i < 8; i++)
#pragma unroll
                for (int j = 0; j < 8; j++) acc[i][j] += ra[i] * rb[j];
        }
        __syncthreads();
    }

#pragma unroll
    for (int i = 0; i < 8; i++) {
        int r = ty * 8 + i;
        if (r < nv) {
            float* hp = g_H + (size_t)(row0 + r) * DF + nb + tx * 8;
            const float* bb = b1 + e * DF + nb + tx * 8;
#pragma unroll
            for (int j = 0; j < 8; j++) {
                float v = acc[i][j] + bb[j];
                hp[j] = v > 0.f ? v : 0.f;
            }
        }
    }
}

// -------- GEMM2: out[tok, m] = H[row, :] @ w2[e][m, :] + b2[e][m]
__global__ __launch_bounds__(256, 2)
void gemm2_kernel(const float* __restrict__ w2,
                  const float* __restrict__ b2,
                  float* __restrict__ out) {
    int slot = blockIdx.y;
    if (slot >= g_nslots) return;
    int e    = g_slot_e[slot];
    int row0 = g_slot_row0[slot];
    int nv   = g_slot_nv[slot];
    const float* Bp = w2 + (size_t)e * DM * DF;
    int nb = blockIdx.x * BN;

    __shared__ float As[BK][BM + 4];
    __shared__ float Bs[BK][BN + 4];
    __shared__ int   toks[BM];

    int tid = threadIdx.x;
    if (tid < BM) toks[tid] = g_perm[row0 + min(tid, nv - 1)];
    __syncthreads();

    int arow = tid >> 1;
    int ak   = (tid & 1) * 4;
    const float* Arowp = g_H + (size_t)(row0 + arow) * DF + ak;
    const float* Browp = Bp + (size_t)(nb + arow) * DF + ak;

    int tx = tid & 15, ty = tid >> 4;

    float acc[8][8];
#pragma unroll
    for (int i = 0; i < 8; i++)
#pragma unroll
        for (int j = 0; j < 8; j++) acc[i][j] = 0.f;

    float4 a_reg = *(const float4*)(Arowp);
    float4 b_reg = *(const float4*)(Browp);

    for (int k0 = 0; k0 < DF; k0 += BK) {
        As[ak + 0][arow] = a_reg.x; As[ak + 1][arow] = a_reg.y;
        As[ak + 2][arow] = a_reg.z; As[ak + 3][arow] = a_reg.w;
        Bs[ak + 0][arow] = b_reg.x; Bs[ak + 1][arow] = b_reg.y;
        Bs[ak + 2][arow] = b_reg.z; Bs[ak + 3][arow] = b_reg.w;
        __syncthreads();
        if (k0 + BK < DF) {
            a_reg = *(const float4*)(Arowp + k0 + BK);
            b_reg = *(const float4*)(Browp + k0 + BK);
        }
#pragma unroll
        for (int k = 0; k < BK; k++) {
            float ra[8], rb[8];
#pragma unroll
            for (int i = 0; i < 8; i++) ra[i] = As[k][ty * 8 + i];
#pragma unroll
            for (int j = 0; j < 8; j++) rb[j] = Bs[k][tx * 8 + j];
#pragma unroll
            for (int i = 0; i < 8; i++)
#pragma unroll
                for (int j = 0; j < 8; j++) acc[i][j] += ra[i] * rb[j];
        }
        __syncthreads();
    }

#pragma unroll
    for (int i = 0; i < 8; i++) {
        int r = ty * 8 + i;
        if (r < nv) {
            int tok = toks[r];
            float* op = out + (size_t)tok * DM + nb + tx * 8;
            const float* bb = b2 + e * DM + nb + tx * 8;
#pragma unroll
            for (int j = 0; j < 8; j++) op[j] = acc[i][j] + bb[j];
        }
    }
}

// ------------------------------- launch ------------------------------------
extern "C" void kernel_launch(void* const* d_in, const int* in_sizes, int n_in,
                              void* d_out, int out_size) {
    const float* x  = (const float*)d_in[0];
    const float* sw = (const float*)d_in[1];
    const float* sb = (const float*)d_in[2];
    const float* w1 = (const float*)d_in[3];
    const float* b1 = (const float*)d_in[4];
    const float* w2 = (const float*)d_in[5];
    const float* b2 = (const float*)d_in[6];
    float* out = (float*)d_out;

    init_kernel<<<1, 32>>>();
    router_kernel<<<T_TOK / 8, 256>>>(x, sw, sb, out + OFF_PMAX);
    finalize_kernel<<<1, 256>>>(out);
    scatter_kernel<<<T_TOK / 256, 256>>>();
    gemm1_kernel<<<dim3(DF / BN, 72), 256>>>(x, w1, b1);
    gemm2_kernel<<<dim3(DM / BN, 72), 256>>>(w2, b2, out);
}

// round 5
// speedup vs baseline: 2.8358x; 2.8358x over previous
#include <cuda_runtime.h>
#include <cuda_bf16.h>
#include <cuda.h>
#include <cstdint>

// ---------------------------------------------------------------------------
// SwitchFeedForward top-1 MoE FFN. T=8192, d_model=1024, d_ff=4096, E=8.
// Round 4: resubmit of round-3 design (infra failure last round) with the
// producer-warp early-return-before-__syncthreads hazard fixed.
// TMA + mbarrier pipeline + ldmatrix + mma.sync.m16n8k16 bf16, hi/lo split
// (3 products, fp32 accum) for fp32-grade accuracy.
// ---------------------------------------------------------------------------

#define T_TOK   8192
#define DM      1024
#define DF      4096
#define NE      8

#define OFF_CNT   (T_TOK * DM)
#define OFF_PSUM  (OFF_CNT + NE)
#define OFF_ZERO  (OFF_PSUM + NE)
#define OFF_PMAX  (OFF_ZERO + 1)

#define BM 128
#define BN 256
#define BKE 32                 // k elems per block (64 bytes per row, SW64)
#define MAX_SLOTS 80

#define A_BYTES   8192         // 128 rows * 64B
#define B_BYTES   16384        // 256 rows * 64B
#define STG       49152        // Ahi+Alo+Bhi+Blo
#define STAGES    4
#define BAR_OFF   (STAGES * STG)          // 196608
#define TOKS_OFF  (BAR_OFF + 64)
#define SMEM_TOTAL (TOKS_OFF + 512)       // 197184

// ----------------------------- device scratch ------------------------------
__device__ __nv_bfloat16 g_Xhi[(size_t)T_TOK * DM];
__device__ __nv_bfloat16 g_Xlo[(size_t)T_TOK * DM];
__device__ __nv_bfloat16 g_w1hi[(size_t)NE * DF * DM];
__device__ __nv_bfloat16 g_w1lo[(size_t)NE * DF * DM];
__device__ __nv_bfloat16 g_w2hi[(size_t)NE * DM * DF];
__device__ __nv_bfloat16 g_w2lo[(size_t)NE * DM * DF];
__device__ __nv_bfloat16 g_Hhi[(size_t)T_TOK * DF];
__device__ __nv_bfloat16 g_Hlo[(size_t)T_TOK * DF];

__device__ float g_probs[T_TOK * NE];
__device__ int   g_routes[T_TOK];
__device__ int   g_cnt[NE];
__device__ int   g_off[NE];
__device__ int   g_fill[NE];
__device__ int   g_perm[T_TOK];
__device__ int   g_slot_e[MAX_SLOTS];
__device__ int   g_slot_row0[MAX_SLOTS];
__device__ int   g_slot_nv[MAX_SLOTS];
__device__ int   g_nslots;

// ----------------------------- PTX helpers ---------------------------------
__device__ __forceinline__ uint32_t s2u(const void* p) {
    uint32_t a;
    asm("{ .reg .u64 t; cvta.to.shared.u64 t, %1; cvt.u32.u64 %0, t; }" : "=r"(a) : "l"(p));
    return a;
}

#define MBAR_INIT(a, c) \
    asm volatile("mbarrier.init.shared.b64 [%0], %1;" :: "r"(a), "r"(c) : "memory")
#define MBAR_EXPECT(a, b) \
    asm volatile("mbarrier.arrive.expect_tx.shared.b64 _, [%0], %1;" :: "r"(a), "r"(b) : "memory")
#define MBAR_ARRIVE(a) \
    asm volatile("mbarrier.arrive.shared.b64 _, [%0];" :: "r"(a) : "memory")

__device__ __forceinline__ void mbar_wait(uint32_t a, uint32_t par) {
    asm volatile(
        "{\n\t.reg .pred P;\n\t"
        "WL%=:\n\t"
        "mbarrier.try_wait.parity.acquire.cta.shared::cta.b64 P, [%0], %1, 0x989680;\n\t"
        "@P bra WD%=;\n\t"
        "bra WL%=;\n\t"
        "WD%=:\n\t}"
        :: "r"(a), "r"(par) : "memory");
}

__device__ __forceinline__ void tma2d(uint32_t dst, const CUtensorMap* m, int cx, int cy, uint32_t mbar) {
    asm volatile(
        "cp.async.bulk.tensor.2d.shared::cta.global.tile.mbarrier::complete_tx::bytes "
        "[%0], [%1, {%2, %3}], [%4];"
        :: "r"(dst), "l"(m), "r"(cx), "r"(cy), "r"(mbar) : "memory");
}

#define LDSM_X4(r0, r1, r2, r3, addr) \
    asm volatile("ldmatrix.sync.aligned.m8n8.x4.shared.b16 {%0,%1,%2,%3}, [%4];" \
        : "=r"(r0), "=r"(r1), "=r"(r2), "=r"(r3) : "r"(addr))

#define MMA16816(d, a, b0v, b1v) \
    asm volatile("mma.sync.aligned.m16n8k16.row.col.f32.bf16.bf16.f32 " \
        "{%0,%1,%2,%3}, {%4,%5,%6,%7}, {%8,%9}, {%0,%1,%2,%3};" \
        : "+f"((d)[0]), "+f"((d)[1]), "+f"((d)[2]), "+f"((d)[3]) \
        : "r"((a)[0]), "r"((a)[1]), "r"((a)[2]), "r"((a)[3]), "r"(b0v), "r"(b1v))

// ----------------------------- small kernels -------------------------------
__global__ void init_kernel() {
    if (threadIdx.x < NE) g_cnt[threadIdx.x] = 0;
}

__global__ void router_kernel(const float* __restrict__ x,
                              const float* __restrict__ sw,
                              const float* __restrict__ sb,
                              float* __restrict__ out_pmax) {
    int warp = threadIdx.x >> 5;
    int lane = threadIdx.x & 31;
    int t = blockIdx.x * 8 + warp;
    if (t >= T_TOK) return;

    const float* xp = x + (size_t)t * DM;
    float acc[NE];
#pragma unroll
    for (int e = 0; e < NE; e++) acc[e] = 0.f;
#pragma unroll 4
    for (int j = 0; j < DM / 32; j++) {
        int idx = lane + 32 * j;
        float xv = xp[idx];
#pragma unroll
        for (int e = 0; e < NE; e++) acc[e] += xv * sw[e * DM + idx];
    }
#pragma unroll
    for (int o = 16; o > 0; o >>= 1)
#pragma unroll
        for (int e = 0; e < NE; e++)
            acc[e] += __shfl_xor_sync(0xffffffffu, acc[e], o);

    if (lane == 0) {
        float l[NE], m = -1e30f;
#pragma unroll
        for (int e = 0; e < NE; e++) { l[e] = acc[e] + sb[e]; m = fmaxf(m, l[e]); }
        float p[NE], s = 0.f;
#pragma unroll
        for (int e = 0; e < NE; e++) { p[e] = expf(l[e] - m); s += p[e]; }
        float inv = 1.f / s;
        int best = 0; float bp = p[0];
#pragma unroll
        for (int e = 1; e < NE; e++) if (p[e] > bp) { bp = p[e]; best = e; }
#pragma unroll
        for (int e = 0; e < NE; e++) g_probs[t * NE + e] = p[e] * inv;
        out_pmax[t] = bp * inv;
        g_routes[t] = best;
        atomicAdd(&g_cnt[best], 1);
    }
}

__global__ void finalize_kernel(float* __restrict__ out) {
    int tid = threadIdx.x, warp = tid >> 5, lane = tid & 31;
    if (warp < NE) {
        float sum = 0.f;
        for (int t = lane; t < T_TOK; t += 32) sum += g_probs[t * NE + warp];
#pragma unroll
        for (int o = 16; o > 0; o >>= 1) sum += __shfl_xor_sync(0xffffffffu, sum, o);
        if (lane == 0) out[OFF_PSUM + warp] = sum;
    }
    if (tid == 0) {
        int off = 0, ns = 0;
        for (int e = 0; e < NE; e++) {
            int c = g_cnt[e];
            g_off[e] = off; g_fill[e] = 0;
            out[OFF_CNT + e] = (float)c;
            for (int i = 0; i < c; i += BM) {
                g_slot_e[ns] = e; g_slot_row0[ns] = off + i;
                g_slot_nv[ns] = min(BM, c - i); ns++;
            }
            off += c;
        }
        g_nslots = ns;
        out[OFF_ZERO] = 0.f;
    }
}

__global__ void scatter_kernel() {
    int t = blockIdx.x * blockDim.x + threadIdx.x;
    if (t < T_TOK) {
        int e = g_routes[t];
        int pos = g_off[e] + atomicAdd(&g_fill[e], 1);
        g_perm[pos] = t;
    }
}

__device__ __forceinline__ void split1(float v, unsigned short& h, unsigned short& l) {
    __nv_bfloat16 hb = __float2bfloat16_rn(v);
    __nv_bfloat16 lb = __float2bfloat16_rn(v - __bfloat162float(hb));
    h = __bfloat16_as_ushort(hb);
    l = __bfloat16_as_ushort(lb);
}

__global__ void convert_split_kernel(const float4* __restrict__ src,
                                     uint2* __restrict__ hi, uint2* __restrict__ lo, int n4) {
    int i = blockIdx.x * blockDim.x + threadIdx.x;
    if (i >= n4) return;
    float4 v = src[i];
    unsigned short h0, l0, h1, l1, h2, l2, h3, l3;
    split1(v.x, h0, l0); split1(v.y, h1, l1); split1(v.z, h2, l2); split1(v.w, h3, l3);
    hi[i] = make_uint2((uint32_t)h0 | ((uint32_t)h1 << 16), (uint32_t)h2 | ((uint32_t)h3 << 16));
    lo[i] = make_uint2((uint32_t)l0 | ((uint32_t)l1 << 16), (uint32_t)l2 | ((uint32_t)l3 << 16));
}

__global__ void gather_x_kernel(const float* __restrict__ x) {
    int r = blockIdx.x;
    int t = threadIdx.x;               // 256 threads, 4 floats each
    int tok = g_perm[r];
    float4 v = ((const float4*)(x + (size_t)tok * DM))[t];
    unsigned short h0, l0, h1, l1, h2, l2, h3, l3;
    split1(v.x, h0, l0); split1(v.y, h1, l1); split1(v.z, h2, l2); split1(v.w, h3, l3);
    ((uint2*)g_Xhi)[(size_t)r * (DM / 4) + t] =
        make_uint2((uint32_t)h0 | ((uint32_t)h1 << 16), (uint32_t)h2 | ((uint32_t)h3 << 16));
    ((uint2*)g_Xlo)[(size_t)r * (DM / 4) + t] =
        make_uint2((uint32_t)l0 | ((uint32_t)l1 << 16), (uint32_t)l2 | ((uint32_t)l3 << 16));
}

// ----------------------------- GEMM building blocks ------------------------
// Producer: one thread streams all k-blocks through the 4-stage ring.
__device__ __forceinline__ void produce_all(
    uint32_t sb,
    const CUtensorMap* mAh, const CUtensorMap* mAl,
    const CUtensorMap* mBh, const CUtensorMap* mBl,
    int rowA, int rowB, int nkb)
{
    uint32_t FULL = sb + BAR_OFF, EMPTY = sb + BAR_OFF + 32;
    for (int L = 0; L < nkb; L++) {
        int s = L & 3;
        if (L >= STAGES) mbar_wait(EMPTY + 8 * s, ((L >> 2) - 1) & 1);
        uint32_t stg = sb + s * STG;
        uint32_t fb = FULL + 8 * s;
        MBAR_EXPECT(fb, STG);
        tma2d(stg,                   mAh, L * BKE, rowA, fb);
        tma2d(stg + A_BYTES,         mAl, L * BKE, rowA, fb);
        tma2d(stg + 2 * A_BYTES,     mBh, L * BKE, rowB, fb);
        tma2d(stg + 2 * A_BYTES + B_BYTES, mBl, L * BKE, rowB, fb);
    }
}

// Consumer: 8 warps, warp tile 64x64 (mw in {0,1}, nw in {0..3}).
// SW64 swizzle: byte c within a 64B row, addr = row*64 + (c ^ (((row>>1)&3)<<4)).
__device__ __forceinline__ void consume_all(
    uint32_t sb, int nkb, int lane, int mw, int nw,
    float (&acc)[4][8][4])
{
    int arow_l = (lane & 7) + ((lane >> 3) & 1) * 8;
    uint32_t acolsel = (uint32_t)((lane >> 4) * 16);
    uint32_t apat = (uint32_t)(((arow_l >> 1) & 3) << 4);
    uint32_t aoff[4];
#pragma unroll
    for (int i = 0; i < 4; i++) aoff[i] = (uint32_t)((mw * 64 + i * 16 + arow_l) * 64);

    int brow_l = ((lane >> 4) & 1) * 8 + (lane & 7);
    uint32_t bcolsel = (uint32_t)(((lane >> 3) & 1) * 16);
    uint32_t bpat = (uint32_t)(((brow_l >> 1) & 3) << 4);
    uint32_t boff[4];
#pragma unroll
    for (int jp = 0; jp < 4; jp++) boff[jp] = (uint32_t)((nw * 64 + jp * 16 + brow_l) * 64);

    uint32_t FULL = sb + BAR_OFF, EMPTY = sb + BAR_OFF + 32;

    for (int kb = 0; kb < nkb; kb++) {
        int s = kb & 3;
        mbar_wait(FULL + 8 * s, (kb >> 2) & 1);
        uint32_t stg = sb + s * STG;
#pragma unroll
        for (int st = 0; st < 2; st++) {
            uint32_t kbyte = (uint32_t)(st * 32);
            uint32_t axor = (kbyte + acolsel) ^ apat;
            uint32_t bxor = (kbyte + bcolsel) ^ bpat;
            uint32_t ah[4][4], al[4][4];
#pragma unroll
            for (int i = 0; i < 4; i++) {
                uint32_t ad = stg + aoff[i] + axor;
                LDSM_X4(ah[i][0], ah[i][1], ah[i][2], ah[i][3], ad);
                LDSM_X4(al[i][0], al[i][1], al[i][2], al[i][3], ad + A_BYTES);
            }
#pragma unroll
            for (int jp = 0; jp < 4; jp++) {
                uint32_t bd = stg + 2 * A_BYTES + boff[jp] + bxor;
                uint32_t bh[4], bl[4];
                LDSM_X4(bh[0], bh[1], bh[2], bh[3], bd);
                LDSM_X4(bl[0], bl[1], bl[2], bl[3], bd + B_BYTES);
#pragma unroll
                for (int i = 0; i < 4; i++) {
                    MMA16816(acc[i][2 * jp],     ah[i], bh[0], bh[1]);
                    MMA16816(acc[i][2 * jp],     ah[i], bl[0], bl[1]);
                    MMA16816(acc[i][2 * jp],     al[i], bh[0], bh[1]);
                    MMA16816(acc[i][2 * jp + 1], ah[i], bh[2], bh[3]);
                    MMA16816(acc[i][2 * jp + 1], ah[i], bl[2], bl[3]);
                    MMA16816(acc[i][2 * jp + 1], al[i], bh[2], bh[3]);
                }
            }
        }
        if (lane == 0) MBAR_ARRIVE(EMPTY + 8 * s);
    }
}

// ----------------------------- GEMM kernels --------------------------------
// GEMM1: H[row, nb..nb+255] = relu(Xg @ w1[e]^T + b1[e]); store bf16 hi/lo.
__global__ __launch_bounds__(288, 1)
void gemm1_tc(const __grid_constant__ CUtensorMap mAh,
              const __grid_constant__ CUtensorMap mAl,
              const __grid_constant__ CUtensorMap mBh,
              const __grid_constant__ CUtensorMap mBl,
              const float* __restrict__ bias)
{
    int slot = blockIdx.y;
    if (slot >= g_nslots) return;
    int e = g_slot_e[slot], row0 = g_slot_row0[slot], nv = g_slot_nv[slot];
    int nb = blockIdx.x * BN;

    extern __shared__ __align__(1024) uint8_t smem_buf[];
    uint32_t sb = s2u(smem_buf);
    int tid = threadIdx.x, lane = tid & 31, warp = tid >> 5;

    if (tid == 0) {
        for (int s = 0; s < STAGES; s++) {
            MBAR_INIT(sb + BAR_OFF + 8 * s, 1);
            MBAR_INIT(sb + BAR_OFF + 32 + 8 * s, 8);
        }
    }
    asm volatile("fence.proxy.async.shared::cta;" ::: "memory");
    __syncthreads();   // all 9 warps participate, THEN roles diverge

    if (warp == 8) {
        if (lane == 0)
            produce_all(sb, &mAh, &mAl, &mBh, &mBl, row0, e * DF + nb, DM / BKE);
        return;        // producer warp exits after its work; no more CTA barriers below
    }

    float acc[4][8][4];
#pragma unroll
    for (int i = 0; i < 4; i++)
#pragma unroll
        for (int j = 0; j < 8; j++)
#pragma unroll
            for (int q = 0; q < 4; q++) acc[i][j][q] = 0.f;

    int mw = warp & 1, nw = warp >> 1;
    consume_all(sb, DM / BKE, lane, mw, nw, acc);

    // epilogue: bias + relu + hi/lo split store
    int rb = mw * 64 + (lane >> 2);
    int cbase = nb + nw * 64 + 2 * (lane & 3);
    const float* bb = bias + (size_t)e * DF;
#pragma unroll
    for (int i = 0; i < 4; i++) {
#pragma unroll
        for (int half = 0; half < 2; half++) {
            int r = rb + i * 16 + half * 8;
            if (r < nv) {
                size_t rowg = (size_t)(row0 + r);
#pragma unroll
                for (int j = 0; j < 8; j++) {
                    int colg = cbase + j * 8;
                    float2 bv = *(const float2*)(bb + colg);
                    float v0 = acc[i][j][2 * half]     + bv.x;
                    float v1 = acc[i][j][2 * half + 1] + bv.y;
                    v0 = fmaxf(v0, 0.f);
                    v1 = fmaxf(v1, 0.f);
                    unsigned short h0, l0, h1, l1;
                    split1(v0, h0, l0); split1(v1, h1, l1);
                    *(uint32_t*)(g_Hhi + rowg * DF + colg) = (uint32_t)h0 | ((uint32_t)h1 << 16);
                    *(uint32_t*)(g_Hlo + rowg * DF + colg) = (uint32_t)l0 | ((uint32_t)l1 << 16);
                }
            }
        }
    }
}

// GEMM2: out[tok, nb..nb+255] = H @ w2[e]^T + b2[e]  (scatter to d_out)
__global__ __launch_bounds__(288, 1)
void gemm2_tc(const __grid_constant__ CUtensorMap mAh,
              const __grid_constant__ CUtensorMap mAl,
              const __grid_constant__ CUtensorMap mBh,
              const __grid_constant__ CUtensorMap mBl,
              const float* __restrict__ bias,
              float* __restrict__ out)
{
    int slot = blockIdx.y;
    if (slot >= g_nslots) return;
    int e = g_slot_e[slot], row0 = g_slot_row0[slot], nv = g_slot_nv[slot];
    int nb = blockIdx.x * BN;

    extern __shared__ __align__(1024) uint8_t smem_buf[];
    uint32_t sb = s2u(smem_buf);
    int tid = threadIdx.x, lane = tid & 31, warp = tid >> 5;
    int* toks = (int*)(smem_buf + TOKS_OFF);

    if (tid == 0) {
        for (int s = 0; s < STAGES; s++) {
            MBAR_INIT(sb + BAR_OFF + 8 * s, 1);
            MBAR_INIT(sb + BAR_OFF + 32 + 8 * s, 8);
        }
    }
    if (tid < BM) toks[tid] = g_perm[row0 + min(tid, nv - 1)];
    asm volatile("fence.proxy.async.shared::cta;" ::: "memory");
    __syncthreads();   // all 9 warps participate, THEN roles diverge

    if (warp == 8) {
        if (lane == 0)
            produce_all(sb, &mAh, &mAl, &mBh, &mBl, row0, e * DM + nb, DF / BKE);
        return;
    }

    float acc[4][8][4];
#pragma unroll
    for (int i = 0; i < 4; i++)
#pragma unroll
        for (int j = 0; j < 8; j++)
#pragma unroll
            for (int q = 0; q < 4; q++) acc[i][j][q] = 0.f;

    int mw = warp & 1, nw = warp >> 1;
    consume_all(sb, DF / BKE, lane, mw, nw, acc);

    // epilogue: bias + scatter fp32 store
    int rb = mw * 64 + (lane >> 2);
    int cbase = nb + nw * 64 + 2 * (lane & 3);
    const float* bb = bias + (size_t)e * DM;
#pragma unroll
    for (int i = 0; i < 4; i++) {
#pragma unroll
        for (int half = 0; half < 2; half++) {
            int r = rb + i * 16 + half * 8;
            if (r < nv) {
                int tok = toks[r];
                float* op = out + (size_t)tok * DM;
#pragma unroll
                for (int j = 0; j < 8; j++) {
                    int colg = cbase + j * 8;
                    float2 bv = *(const float2*)(bb + colg);
                    float2 v;
                    v.x = acc[i][j][2 * half]     + bv.x;
                    v.y = acc[i][j][2 * half + 1] + bv.y;
                    *(float2*)(op + colg) = v;
                }
            }
        }
    }
}

// ------------------------------- host side ---------------------------------
typedef CUresult (CUDAAPI *PFN_encodeTiled)(
    CUtensorMap*, CUtensorMapDataType, cuuint32_t, void*,
    const cuuint64_t*, const cuuint64_t*, const cuuint32_t*, const cuuint32_t*,
    CUtensorMapInterleave, CUtensorMapSwizzle, CUtensorMapL2promotion, CUtensorMapFloatOOBfill);

static PFN_encodeTiled get_encode_fn() {
    static PFN_encodeTiled fn = nullptr;
    if (!fn) {
        void* p = nullptr;
        cudaDriverEntryPointQueryResult st;
#if CUDART_VERSION >= 12050
        cudaGetDriverEntryPointByVersion("cuTensorMapEncodeTiled", &p, 12000, cudaEnableDefault, &st);
#else
        cudaGetDriverEntryPoint("cuTensorMapEncodeTiled", &p, cudaEnableDefault, &st);
#endif
        fn = (PFN_encodeTiled)p;
    }
    return fn;
}

// 2D bf16 map, SW64, box {32, box_rows}
static void make_map_2d(CUtensorMap* m, void* ptr, uint64_t d0, uint64_t d1, uint32_t box_rows) {
    cuuint64_t gd[2] = {d0, d1};
    cuuint64_t gs[1] = {d0 * 2};
    cuuint32_t box[2] = {BKE, box_rows};
    cuuint32_t es[2] = {1, 1};
    get_encode_fn()(m, CU_TENSOR_MAP_DATA_TYPE_BFLOAT16, 2, ptr, gd, gs, box, es,
                    CU_TENSOR_MAP_INTERLEAVE_NONE, CU_TENSOR_MAP_SWIZZLE_64B,
                    CU_TENSOR_MAP_L2_PROMOTION_L2_128B, CU_TENSOR_MAP_FLOAT_OOB_FILL_NONE);
}

extern "C" void kernel_launch(void* const* d_in, const int* in_sizes, int n_in,
                              void* d_out, int out_size) {
    const float* x  = (const float*)d_in[0];
    const float* sw = (const float*)d_in[1];
    const float* sb = (const float*)d_in[2];
    const float* w1 = (const float*)d_in[3];
    const float* b1 = (const float*)d_in[4];
    const float* w2 = (const float*)d_in[5];
    const float* b2 = (const float*)d_in[6];
    float* out = (float*)d_out;

    void *p_xhi, *p_xlo, *p_w1h, *p_w1l, *p_w2h, *p_w2l, *p_hhi, *p_hlo;
    cudaGetSymbolAddress(&p_xhi, g_Xhi);  cudaGetSymbolAddress(&p_xlo, g_Xlo);
    cudaGetSymbolAddress(&p_w1h, g_w1hi); cudaGetSymbolAddress(&p_w1l, g_w1lo);
    cudaGetSymbolAddress(&p_w2h, g_w2hi); cudaGetSymbolAddress(&p_w2l, g_w2lo);
    cudaGetSymbolAddress(&p_hhi, g_Hhi);  cudaGetSymbolAddress(&p_hlo, g_Hlo);

    CUtensorMap mXh, mXl, mW1h, mW1l, mW2h, mW2l, mHh, mHl;
    make_map_2d(&mXh,  p_xhi, DM, T_TOK, 128);
    make_map_2d(&mXl,  p_xlo, DM, T_TOK, 128);
    make_map_2d(&mW1h, p_w1h, DM, (uint64_t)NE * DF, 256);
    make_map_2d(&mW1l, p_w1l, DM, (uint64_t)NE * DF, 256);
    make_map_2d(&mW2h, p_w2h, DF, (uint64_t)NE * DM, 256);
    make_map_2d(&mW2l, p_w2l, DF, (uint64_t)NE * DM, 256);
    make_map_2d(&mHh,  p_hhi, DF, T_TOK, 128);
    make_map_2d(&mHl,  p_hlo, DF, T_TOK, 128);

    cudaFuncSetAttribute(gemm1_tc, cudaFuncAttributeMaxDynamicSharedMemorySize, SMEM_TOTAL);
    cudaFuncSetAttribute(gemm2_tc, cudaFuncAttributeMaxDynamicSharedMemorySize, SMEM_TOTAL);

    {
        int n4 = NE * DF * DM / 4;
        convert_split_kernel<<<n4 / 256, 256>>>((const float4*)w1, (uint2*)p_w1h, (uint2*)p_w1l, n4);
        convert_split_kernel<<<n4 / 256, 256>>>((const float4*)w2, (uint2*)p_w2h, (uint2*)p_w2l, n4);
    }

    init_kernel<<<1, 32>>>();
    router_kernel<<<T_TOK / 8, 256>>>(x, sw, sb, out + OFF_PMAX);
    finalize_kernel<<<1, 256>>>(out);
    scatter_kernel<<<T_TOK / 256, 256>>>();
    gather_x_kernel<<<T_TOK, 256>>>(x);

    gemm1_tc<<<dim3(DF / BN, 71), 288, SMEM_TOTAL>>>(mXh, mXl, mW1h, mW1l, b1);
    gemm2_tc<<<dim3(DM / BN, 71), 288, SMEM_TOTAL>>>(mHh, mHl, mW2h, mW2l, b2, out);
}

// round 7
// speedup vs baseline: 2.9348x; 1.0349x over previous
#include <cuda_runtime.h>
#include <cuda_bf16.h>
#include <cuda.h>
#include <cstdint>

// ---------------------------------------------------------------------------
// SwitchFeedForward top-1 MoE FFN. T=8192, d_model=1024, d_ff=4096, E=8.
// Round 6: round-4 base (passed, 1278us) + two consumer-loop fixes:
//   (1) product-major MMA ordering (breaks 3-deep accumulator RAW chains)
//   (2) B-fragment double buffering (hides LDSM latency under MMA issue)
// TMA + mbarrier 4-stage pipeline, mma.sync.m16n8k16 bf16 hi/lo split
// (3 products, fp32 accum), 1 CTA/SM, 8 consumer warps + 1 producer warp.
// ---------------------------------------------------------------------------

#define T_TOK   8192
#define DM      1024
#define DF      4096
#define NE      8

#define OFF_CNT   (T_TOK * DM)
#define OFF_PSUM  (OFF_CNT + NE)
#define OFF_ZERO  (OFF_PSUM + NE)
#define OFF_PMAX  (OFF_ZERO + 1)

#define BM 128
#define BN 256
#define BKE 32                 // k elems per block (64 bytes per row, SW64)
#define MAX_SLOTS 80

#define A_BYTES   8192         // 128 rows * 64B
#define B_BYTES   16384        // 256 rows * 64B
#define STG       49152        // Ahi+Alo+Bhi+Blo
#define STAGES    4
#define BAR_OFF   (STAGES * STG)          // 196608
#define TOKS_OFF  (BAR_OFF + 64)
#define SMEM_TOTAL (TOKS_OFF + 512)       // 197184 -> 1 CTA/SM

// ----------------------------- device scratch ------------------------------
__device__ __nv_bfloat16 g_Xhi[(size_t)T_TOK * DM];
__device__ __nv_bfloat16 g_Xlo[(size_t)T_TOK * DM];
__device__ __nv_bfloat16 g_w1hi[(size_t)NE * DF * DM];
__device__ __nv_bfloat16 g_w1lo[(size_t)NE * DF * DM];
__device__ __nv_bfloat16 g_w2hi[(size_t)NE * DM * DF];
__device__ __nv_bfloat16 g_w2lo[(size_t)NE * DM * DF];
__device__ __nv_bfloat16 g_Hhi[(size_t)T_TOK * DF];
__device__ __nv_bfloat16 g_Hlo[(size_t)T_TOK * DF];

__device__ float g_probs[T_TOK * NE];
__device__ int   g_routes[T_TOK];
__device__ int   g_cnt[NE];
__device__ int   g_off[NE];
__device__ int   g_fill[NE];
__device__ int   g_perm[T_TOK];
__device__ int   g_slot_e[MAX_SLOTS];
__device__ int   g_slot_row0[MAX_SLOTS];
__device__ int   g_slot_nv[MAX_SLOTS];
__device__ int   g_nslots;

// ----------------------------- PTX helpers ---------------------------------
__device__ __forceinline__ uint32_t s2u(const void* p) {
    uint32_t a;
    asm("{ .reg .u64 t; cvta.to.shared.u64 t, %1; cvt.u32.u64 %0, t; }" : "=r"(a) : "l"(p));
    return a;
}

#define MBAR_INIT(a, c) \
    asm volatile("mbarrier.init.shared.b64 [%0], %1;" :: "r"(a), "r"(c) : "memory")
#define MBAR_EXPECT(a, b) \
    asm volatile("mbarrier.arrive.expect_tx.shared.b64 _, [%0], %1;" :: "r"(a), "r"(b) : "memory")
#define MBAR_ARRIVE(a) \
    asm volatile("mbarrier.arrive.shared.b64 _, [%0];" :: "r"(a) : "memory")

__device__ __forceinline__ void mbar_wait(uint32_t a, uint32_t par) {
    asm volatile(
        "{\n\t.reg .pred P;\n\t"
        "WL%=:\n\t"
        "mbarrier.try_wait.parity.acquire.cta.shared::cta.b64 P, [%0], %1, 0x989680;\n\t"
        "@P bra WD%=;\n\t"
        "bra WL%=;\n\t"
        "WD%=:\n\t}"
        :: "r"(a), "r"(par) : "memory");
}

__device__ __forceinline__ void tma2d(uint32_t dst, const CUtensorMap* m, int cx, int cy, uint32_t mbar) {
    asm volatile(
        "cp.async.bulk.tensor.2d.shared::cta.global.tile.mbarrier::complete_tx::bytes "
        "[%0], [%1, {%2, %3}], [%4];"
        :: "r"(dst), "l"(m), "r"(cx), "r"(cy), "r"(mbar) : "memory");
}

#define LDSM_X4(r0, r1, r2, r3, addr) \
    asm volatile("ldmatrix.sync.aligned.m8n8.x4.shared.b16 {%0,%1,%2,%3}, [%4];" \
        : "=r"(r0), "=r"(r1), "=r"(r2), "=r"(r3) : "r"(addr))

#define MMA16816(d, a, b0v, b1v) \
    asm volatile("mma.sync.aligned.m16n8k16.row.col.f32.bf16.bf16.f32 " \
        "{%0,%1,%2,%3}, {%4,%5,%6,%7}, {%8,%9}, {%0,%1,%2,%3};" \
        : "+f"((d)[0]), "+f"((d)[1]), "+f"((d)[2]), "+f"((d)[3]) \
        : "r"((a)[0]), "r"((a)[1]), "r"((a)[2]), "r"((a)[3]), "r"(b0v), "r"(b1v))

// ----------------------------- small kernels -------------------------------
__global__ void init_kernel() {
    if (threadIdx.x < NE) g_cnt[threadIdx.x] = 0;
}

__global__ void router_kernel(const float* __restrict__ x,
                              const float* __restrict__ sw,
                              const float* __restrict__ sb,
                              float* __restrict__ out_pmax) {
    int warp = threadIdx.x >> 5;
    int lane = threadIdx.x & 31;
    int t = blockIdx.x * 8 + warp;
    if (t >= T_TOK) return;

    const float* xp = x + (size_t)t * DM;
    float acc[NE];
#pragma unroll
    for (int e = 0; e < NE; e++) acc[e] = 0.f;
#pragma unroll 4
    for (int j = 0; j < DM / 32; j++) {
        int idx = lane + 32 * j;
        float xv = xp[idx];
#pragma unroll
        for (int e = 0; e < NE; e++) acc[e] += xv * sw[e * DM + idx];
    }
#pragma unroll
    for (int o = 16; o > 0; o >>= 1)
#pragma unroll
        for (int e = 0; e < NE; e++)
            acc[e] += __shfl_xor_sync(0xffffffffu, acc[e], o);

    if (lane == 0) {
        float l[NE], m = -1e30f;
#pragma unroll
        for (int e = 0; e < NE; e++) { l[e] = acc[e] + sb[e]; m = fmaxf(m, l[e]); }
        float p[NE], s = 0.f;
#pragma unroll
        for (int e = 0; e < NE; e++) { p[e] = expf(l[e] - m); s += p[e]; }
        float inv = 1.f / s;
        int best = 0; float bp = p[0];
#pragma unroll
        for (int e = 1; e < NE; e++) if (p[e] > bp) { bp = p[e]; best = e; }
#pragma unroll
        for (int e = 0; e < NE; e++) g_probs[t * NE + e] = p[e] * inv;
        out_pmax[t] = bp * inv;
        g_routes[t] = best;
        atomicAdd(&g_cnt[best], 1);
    }
}

__global__ void finalize_kernel(float* __restrict__ out) {
    int tid = threadIdx.x, warp = tid >> 5, lane = tid & 31;
    if (warp < NE) {
        float sum = 0.f;
        for (int t = lane; t < T_TOK; t += 32) sum += g_probs[t * NE + warp];
#pragma unroll
        for (int o = 16; o > 0; o >>= 1) sum += __shfl_xor_sync(0xffffffffu, sum, o);
        if (lane == 0) out[OFF_PSUM + warp] = sum;
    }
    if (tid == 0) {
        int off = 0, ns = 0;
        for (int e = 0; e < NE; e++) {
            int c = g_cnt[e];
            g_off[e] = off; g_fill[e] = 0;
            out[OFF_CNT + e] = (float)c;
            for (int i = 0; i < c; i += BM) {
                g_slot_e[ns] = e; g_slot_row0[ns] = off + i;
                g_slot_nv[ns] = min(BM, c - i); ns++;
            }
            off += c;
        }
        g_nslots = ns;
        out[OFF_ZERO] = 0.f;
    }
}

__global__ void scatter_kernel() {
    int t = blockIdx.x * blockDim.x + threadIdx.x;
    if (t < T_TOK) {
        int e = g_routes[t];
        int pos = g_off[e] + atomicAdd(&g_fill[e], 1);
        g_perm[pos] = t;
    }
}

__device__ __forceinline__ void split1(float v, unsigned short& h, unsigned short& l) {
    __nv_bfloat16 hb = __float2bfloat16_rn(v);
    __nv_bfloat16 lb = __float2bfloat16_rn(v - __bfloat162float(hb));
    h = __bfloat16_as_ushort(hb);
    l = __bfloat16_as_ushort(lb);
}

__global__ void convert_split_kernel(const float4* __restrict__ src,
                                     uint2* __restrict__ hi, uint2* __restrict__ lo, int n4) {
    int i = blockIdx.x * blockDim.x + threadIdx.x;
    if (i >= n4) return;
    float4 v = src[i];
    unsigned short h0, l0, h1, l1, h2, l2, h3, l3;
    split1(v.x, h0, l0); split1(v.y, h1, l1); split1(v.z, h2, l2); split1(v.w, h3, l3);
    hi[i] = make_uint2((uint32_t)h0 | ((uint32_t)h1 << 16), (uint32_t)h2 | ((uint32_t)h3 << 16));
    lo[i] = make_uint2((uint32_t)l0 | ((uint32_t)l1 << 16), (uint32_t)l2 | ((uint32_t)l3 << 16));
}

__global__ void gather_x_kernel(const float* __restrict__ x) {
    int r = blockIdx.x;
    int t = threadIdx.x;               // 256 threads, 4 floats each
    int tok = g_perm[r];
    float4 v = ((const float4*)(x + (size_t)tok * DM))[t];
    unsigned short h0, l0, h1, l1, h2, l2, h3, l3;
    split1(v.x, h0, l0); split1(v.y, h1, l1); split1(v.z, h2, l2); split1(v.w, h3, l3);
    ((uint2*)g_Xhi)[(size_t)r * (DM / 4) + t] =
        make_uint2((uint32_t)h0 | ((uint32_t)h1 << 16), (uint32_t)h2 | ((uint32_t)h3 << 16));
    ((uint2*)g_Xlo)[(size_t)r * (DM / 4) + t] =
        make_uint2((uint32_t)l0 | ((uint32_t)l1 << 16), (uint32_t)l2 | ((uint32_t)l3 << 16));
}

// ----------------------------- GEMM building blocks ------------------------
// Producer: one thread streams all k-blocks through the 4-stage ring.
__device__ __forceinline__ void produce_all(
    uint32_t sb,
    const CUtensorMap* mAh, const CUtensorMap* mAl,
    const CUtensorMap* mBh, const CUtensorMap* mBl,
    int rowA, int rowB, int nkb)
{
    uint32_t FULL = sb + BAR_OFF, EMPTY = sb + BAR_OFF + 32;
    for (int L = 0; L < nkb; L++) {
        int s = L & (STAGES - 1);
        if (L >= STAGES) mbar_wait(EMPTY + 8 * s, ((L / STAGES) - 1) & 1);
        uint32_t stg = sb + s * STG;
        uint32_t fb = FULL + 8 * s;
        MBAR_EXPECT(fb, STG);
        tma2d(stg,                   mAh, L * BKE, rowA, fb);
        tma2d(stg + A_BYTES,         mAl, L * BKE, rowA, fb);
        tma2d(stg + 2 * A_BYTES,     mBh, L * BKE, rowB, fb);
        tma2d(stg + 2 * A_BYTES + B_BYTES, mBl, L * BKE, rowB, fb);
    }
}

// Consumer: 8 warps, warp tile 64x64 (mw in {0,1}, nw in {0..3}).
// SW64 swizzle: byte c within a 64B row, addr = row*64 + (c ^ (((row>>1)&3)<<4)).
// Round-6: product-major MMA order (no acc RAW chains) + B double buffering.
__device__ __forceinline__ void consume_all(
    uint32_t sb, int nkb, int lane, int mw, int nw,
    float (&acc)[4][8][4])
{
    int arow_l = (lane & 7) + ((lane >> 3) & 1) * 8;
    uint32_t acolsel = (uint32_t)((lane >> 4) * 16);
    uint32_t apat = (uint32_t)(((arow_l >> 1) & 3) << 4);
    uint32_t aoff[4];
#pragma unroll
    for (int i = 0; i < 4; i++) aoff[i] = (uint32_t)((mw * 64 + i * 16 + arow_l) * 64);

    int brow_l = ((lane >> 4) & 1) * 8 + (lane & 7);
    uint32_t bcolsel = (uint32_t)(((lane >> 3) & 1) * 16);
    uint32_t bpat = (uint32_t)(((brow_l >> 1) & 3) << 4);
    uint32_t boff[4];
#pragma unroll
    for (int jp = 0; jp < 4; jp++) boff[jp] = (uint32_t)((nw * 64 + jp * 16 + brow_l) * 64);

    uint32_t FULL = sb + BAR_OFF, EMPTY = sb + BAR_OFF + 32;

    for (int kb = 0; kb < nkb; kb++) {
        int s = kb & (STAGES - 1);
        mbar_wait(FULL + 8 * s, (kb / STAGES) & 1);
        uint32_t stg = sb + s * STG;
#pragma unroll
        for (int st = 0; st < 2; st++) {
            uint32_t kbyte = (uint32_t)(st * 32);
            uint32_t axor = (kbyte + acolsel) ^ apat;
            uint32_t bxor = (kbyte + bcolsel) ^ bpat;
            uint32_t ah[4][4], al[4][4];
#pragma unroll
            for (int i = 0; i < 4; i++) {
                uint32_t ad = stg + aoff[i] + axor;
                LDSM_X4(ah[i][0], ah[i][1], ah[i][2], ah[i][3], ad);
                LDSM_X4(al[i][0], al[i][1], al[i][2], al[i][3], ad + A_BYTES);
            }
            // double-buffered B fragments
            uint32_t bh[2][4], bl[2][4];
            {
                uint32_t bd0 = stg + 2 * A_BYTES + boff[0] + bxor;
                LDSM_X4(bh[0][0], bh[0][1], bh[0][2], bh[0][3], bd0);
                LDSM_X4(bl[0][0], bl[0][1], bl[0][2], bl[0][3], bd0 + B_BYTES);
            }
#pragma unroll
            for (int jp = 0; jp < 4; jp++) {
                int cur = jp & 1;
                int nxt = cur ^ 1;
                if (jp < 3) {
                    uint32_t bdn = stg + 2 * A_BYTES + boff[jp + 1] + bxor;
                    LDSM_X4(bh[nxt][0], bh[nxt][1], bh[nxt][2], bh[nxt][3], bdn);
                    LDSM_X4(bl[nxt][0], bl[nxt][1], bl[nxt][2], bl[nxt][3], bdn + B_BYTES);
                }
                // product-major: same acc reused only every 8 MMAs
#pragma unroll
                for (int i = 0; i < 4; i++) {
                    MMA16816(acc[i][2 * jp],     ah[i], bh[cur][0], bh[cur][1]);
                    MMA16816(acc[i][2 * jp + 1], ah[i], bh[cur][2], bh[cur][3]);
                }
#pragma unroll
                for (int i = 0; i < 4; i++) {
                    MMA16816(acc[i][2 * jp],     ah[i], bl[cur][0], bl[cur][1]);
                    MMA16816(acc[i][2 * jp + 1], ah[i], bl[cur][2], bl[cur][3]);
                }
#pragma unroll
                for (int i = 0; i < 4; i++) {
                    MMA16816(acc[i][2 * jp],     al[i], bh[cur][0], bh[cur][1]);
                    MMA16816(acc[i][2 * jp + 1], al[i], bh[cur][2], bh[cur][3]);
                }
            }
        }
        if (lane == 0) MBAR_ARRIVE(EMPTY + 8 * s);
    }
}

// ----------------------------- GEMM kernels --------------------------------
// GEMM1: H[row, nb..nb+255] = relu(Xg @ w1[e]^T + b1[e]); store bf16 hi/lo.
__global__ __launch_bounds__(288, 1)
void gemm1_tc(const __grid_constant__ CUtensorMap mAh,
              const __grid_constant__ CUtensorMap mAl,
              const __grid_constant__ CUtensorMap mBh,
              const __grid_constant__ CUtensorMap mBl,
              const float* __restrict__ bias)
{
    int slot = blockIdx.y;
    if (slot >= g_nslots) return;
    int e = g_slot_e[slot], row0 = g_slot_row0[slot], nv = g_slot_nv[slot];
    int nb = blockIdx.x * BN;

    extern __shared__ __align__(1024) uint8_t smem_buf[];
    uint32_t sb = s2u(smem_buf);
    int tid = threadIdx.x, lane = tid & 31, warp = tid >> 5;

    if (tid == 0) {
        for (int s = 0; s < STAGES; s++) {
            MBAR_INIT(sb + BAR_OFF + 8 * s, 1);
            MBAR_INIT(sb + BAR_OFF + 32 + 8 * s, 8);
        }
    }
    asm volatile("fence.proxy.async.shared::cta;" ::: "memory");
    __syncthreads();   // all 9 warps participate, THEN roles diverge

    if (warp == 8) {
        if (lane == 0)
            produce_all(sb, &mAh, &mAl, &mBh, &mBl, row0, e * DF + nb, DM / BKE);
        return;
    }

    float acc[4][8][4];
#pragma unroll
    for (int i = 0; i < 4; i++)
#pragma unroll
        for (int j = 0; j < 8; j++)
#pragma unroll
            for (int q = 0; q < 4; q++) acc[i][j][q] = 0.f;

    int mw = warp & 1, nw = warp >> 1;
    consume_all(sb, DM / BKE, lane, mw, nw, acc);

    // epilogue: bias + relu + hi/lo split store
    int rb = mw * 64 + (lane >> 2);
    int cbase = nb + nw * 64 + 2 * (lane & 3);
    const float* bb = bias + (size_t)e * DF;
#pragma unroll
    for (int i = 0; i < 4; i++) {
#pragma unroll
        for (int half = 0; half < 2; half++) {
            int r = rb + i * 16 + half * 8;
            if (r < nv) {
                size_t rowg = (size_t)(row0 + r);
#pragma unroll
                for (int j = 0; j < 8; j++) {
                    int colg = cbase + j * 8;
                    float2 bv = *(const float2*)(bb + colg);
                    float v0 = acc[i][j][2 * half]     + bv.x;
                    float v1 = acc[i][j][2 * half + 1] + bv.y;
                    v0 = fmaxf(v0, 0.f);
                    v1 = fmaxf(v1, 0.f);
                    unsigned short h0, l0, h1, l1;
                    split1(v0, h0, l0); split1(v1, h1, l1);
                    *(uint32_t*)(g_Hhi + rowg * DF + colg) = (uint32_t)h0 | ((uint32_t)h1 << 16);
                    *(uint32_t*)(g_Hlo + rowg * DF + colg) = (uint32_t)l0 | ((uint32_t)l1 << 16);
                }
            }
        }
    }
}

// GEMM2: out[tok, nb..nb+255] = H @ w2[e]^T + b2[e]  (scatter to d_out)
__global__ __launch_bounds__(288, 1)
void gemm2_tc(const __grid_constant__ CUtensorMap mAh,
              const __grid_constant__ CUtensorMap mAl,
              const __grid_constant__ CUtensorMap mBh,
              const __grid_constant__ CUtensorMap mBl,
              const float* __restrict__ bias,
              float* __restrict__ out)
{
    int slot = blockIdx.y;
    if (slot >= g_nslots) return;
    int e = g_slot_e[slot], row0 = g_slot_row0[slot], nv = g_slot_nv[slot];
    int nb = blockIdx.x * BN;

    extern __shared__ __align__(1024) uint8_t smem_buf[];
    uint32_t sb = s2u(smem_buf);
    int tid = threadIdx.x, lane = tid & 31, warp = tid >> 5;
    int* toks = (int*)(smem_buf + TOKS_OFF);

    if (tid == 0) {
        for (int s = 0; s < STAGES; s++) {
            MBAR_INIT(sb + BAR_OFF + 8 * s, 1);
            MBAR_INIT(sb + BAR_OFF + 32 + 8 * s, 8);
        }
    }
    if (tid < BM) toks[tid] = g_perm[row0 + min(tid, nv - 1)];
    asm volatile("fence.proxy.async.shared::cta;" ::: "memory");
    __syncthreads();   // all 9 warps participate, THEN roles diverge

    if (warp == 8) {
        if (lane == 0)
            produce_all(sb, &mAh, &mAl, &mBh, &mBl, row0, e * DM + nb, DF / BKE);
        return;
    }

    float acc[4][8][4];
#pragma unroll
    for (int i = 0; i < 4; i++)
#pragma unroll
        for (int j = 0; j < 8; j++)
#pragma unroll
            for (int q = 0; q < 4; q++) acc[i][j][q] = 0.f;

    int mw = warp & 1, nw = warp >> 1;
    consume_all(sb, DF / BKE, lane, mw, nw, acc);

    // epilogue: bias + scatter fp32 store
    int rb = mw * 64 + (lane >> 2);
    int cbase = nb + nw * 64 + 2 * (lane & 3);
    const float* bb = bias + (size_t)e * DM;
#pragma unroll
    for (int i = 0; i < 4; i++) {
#pragma unroll
        for (int half = 0; half < 2; half++) {
            int r = rb + i * 16 + half * 8;
            if (r < nv) {
                int tok = toks[r];
                float* op = out + (size_t)tok * DM;
#pragma unroll
                for (int j = 0; j < 8; j++) {
                    int colg = cbase + j * 8;
                    float2 bv = *(const float2*)(bb + colg);
                    float2 v;
                    v.x = acc[i][j][2 * half]     + bv.x;
                    v.y = acc[i][j][2 * half + 1] + bv.y;
                    *(float2*)(op + colg) = v;
                }
            }
        }
    }
}

// ------------------------------- host side ---------------------------------
typedef CUresult (CUDAAPI *PFN_encodeTiled)(
    CUtensorMap*, CUtensorMapDataType, cuuint32_t, void*,
    const cuuint64_t*, const cuuint64_t*, const cuuint32_t*, const cuuint32_t*,
    CUtensorMapInterleave, CUtensorMapSwizzle, CUtensorMapL2promotion, CUtensorMapFloatOOBfill);

static PFN_encodeTiled get_encode_fn() {
    static PFN_encodeTiled fn = nullptr;
    if (!fn) {
        void* p = nullptr;
        cudaDriverEntryPointQueryResult st;
#if CUDART_VERSION >= 12050
        cudaGetDriverEntryPointByVersion("cuTensorMapEncodeTiled", &p, 12000, cudaEnableDefault, &st);
#else
        cudaGetDriverEntryPoint("cuTensorMapEncodeTiled", &p, cudaEnableDefault, &st);
#endif
        fn = (PFN_encodeTiled)p;
    }
    return fn;
}

// 2D bf16 map, SW64, box {32, box_rows}
static void make_map_2d(CUtensorMap* m, void* ptr, uint64_t d0, uint64_t d1, uint32_t box_rows) {
    cuuint64_t gd[2] = {d0, d1};
    cuuint64_t gs[1] = {d0 * 2};
    cuuint32_t box[2] = {BKE, box_rows};
    cuuint32_t es[2] = {1, 1};
    get_encode_fn()(m, CU_TENSOR_MAP_DATA_TYPE_BFLOAT16, 2, ptr, gd, gs, box, es,
                    CU_TENSOR_MAP_INTERLEAVE_NONE, CU_TENSOR_MAP_SWIZZLE_64B,
                    CU_TENSOR_MAP_L2_PROMOTION_L2_128B, CU_TENSOR_MAP_FLOAT_OOB_FILL_NONE);
}

extern "C" void kernel_launch(void* const* d_in, const int* in_sizes, int n_in,
                              void* d_out, int out_size) {
    const float* x  = (const float*)d_in[0];
    const float* sw = (const float*)d_in[1];
    const float* sb = (const float*)d_in[2];
    const float* w1 = (const float*)d_in[3];
    const float* b1 = (const float*)d_in[4];
    const float* w2 = (const float*)d_in[5];
    const float* b2 = (const float*)d_in[6];
    float* out = (float*)d_out;

    void *p_xhi, *p_xlo, *p_w1h, *p_w1l, *p_w2h, *p_w2l, *p_hhi, *p_hlo;
    cudaGetSymbolAddress(&p_xhi, g_Xhi);  cudaGetSymbolAddress(&p_xlo, g_Xlo);
    cudaGetSymbolAddress(&p_w1h, g_w1hi); cudaGetSymbolAddress(&p_w1l, g_w1lo);
    cudaGetSymbolAddress(&p_w2h, g_w2hi); cudaGetSymbolAddress(&p_w2l, g_w2lo);
    cudaGetSymbolAddress(&p_hhi, g_Hhi);  cudaGetSymbolAddress(&p_hlo, g_Hlo);

    CUtensorMap mXh, mXl, mW1h, mW1l, mW2h, mW2l, mHh, mHl;
    make_map_2d(&mXh,  p_xhi, DM, T_TOK, 128);
    make_map_2d(&mXl,  p_xlo, DM, T_TOK, 128);
    make_map_2d(&mW1h, p_w1h, DM, (uint64_t)NE * DF, 256);
    make_map_2d(&mW1l, p_w1l, DM, (uint64_t)NE * DF, 256);
    make_map_2d(&mW2h, p_w2h, DF, (uint64_t)NE * DM, 256);
    make_map_2d(&mW2l, p_w2l, DF, (uint64_t)NE * DM, 256);
    make_map_2d(&mHh,  p_hhi, DF, T_TOK, 128);
    make_map_2d(&mHl,  p_hlo, DF, T_TOK, 128);

    cudaFuncSetAttribute(gemm1_tc, cudaFuncAttributeMaxDynamicSharedMemorySize, SMEM_TOTAL);
    cudaFuncSetAttribute(gemm2_tc, cudaFuncAttributeMaxDynamicSharedMemorySize, SMEM_TOTAL);

    {
        int n4 = NE * DF * DM / 4;
        convert_split_kernel<<<n4 / 256, 256>>>((const float4*)w1, (uint2*)p_w1h, (uint2*)p_w1l, n4);
        convert_split_kernel<<<n4 / 256, 256>>>((const float4*)w2, (uint2*)p_w2h, (uint2*)p_w2l, n4);
    }

    init_kernel<<<1, 32>>>();
    router_kernel<<<T_TOK / 8, 256>>>(x, sw, sb, out + OFF_PMAX);
    finalize_kernel<<<1, 256>>>(out);
    scatter_kernel<<<T_TOK / 256, 256>>>();
    gather_x_kernel<<<T_TOK, 256>>>(x);

    gemm1_tc<<<dim3(DF / BN, 71), 288, SMEM_TOTAL>>>(mXh, mXl, mW1h, mW1l, b1);
    gemm2_tc<<<dim3(DM / BN, 71), 288, SMEM_TOTAL>>>(mHh, mHl, mW2h, mW2l, b2, out);
}

// round 9
// speedup vs baseline: 4.1834x; 1.4254x over previous
#include <cuda_runtime.h>
#include <cuda_fp16.h>
#include <cuda.h>
#include <cstdint>

// ---------------------------------------------------------------------------
// SwitchFeedForward top-1 MoE FFN. T=8192, d_model=1024, d_ff=4096, E=8.
// Round 8: byte-identical resubmit of round-7 (infra failed twice; design
// untested). fp16 asymmetric split: A-side (tokens) = hi+lo fp16, B-side
// (weights) = single fp16. 2 MMA products instead of 3 (HMMA count x2/3,
// B traffic x1/2). fp32 accum. Predicted rel_err ~3e-4.
// ---------------------------------------------------------------------------

#define T_TOK   8192
#define DM      1024
#define DF      4096
#define NE      8

#define OFF_CNT   (T_TOK * DM)
#define OFF_PSUM  (OFF_CNT + NE)
#define OFF_ZERO  (OFF_PSUM + NE)
#define OFF_PMAX  (OFF_ZERO + 1)

#define BM 128
#define BN 256
#define BKE 32                 // k elems per block (64 bytes per row, SW64)
#define MAX_SLOTS 80

#define A_BYTES   8192         // 128 rows * 64B
#define B_BYTES   16384        // 256 rows * 64B
#define STG       32768        // Ahi + Alo + Bh
#define STAGES    4
#define BAR_OFF   (STAGES * STG)          // 131072
#define TOKS_OFF  (BAR_OFF + 64)
#define SMEM_TOTAL (TOKS_OFF + 512)       // 131648 -> 1 CTA/SM

// ----------------------------- device scratch ------------------------------
__device__ __half g_Xhi[(size_t)T_TOK * DM];
__device__ __half g_Xlo[(size_t)T_TOK * DM];
__device__ __half g_w1h[(size_t)NE * DF * DM];
__device__ __half g_w2h[(size_t)NE * DM * DF];
__device__ __half g_Hhi[(size_t)T_TOK * DF];
__device__ __half g_Hlo[(size_t)T_TOK * DF];

__device__ float g_probs[T_TOK * NE];
__device__ int   g_routes[T_TOK];
__device__ int   g_cnt[NE];
__device__ int   g_off[NE];
__device__ int   g_fill[NE];
__device__ int   g_perm[T_TOK];
__device__ int   g_slot_e[MAX_SLOTS];
__device__ int   g_slot_row0[MAX_SLOTS];
__device__ int   g_slot_nv[MAX_SLOTS];
__device__ int   g_nslots;

// ----------------------------- PTX helpers ---------------------------------
__device__ __forceinline__ uint32_t s2u(const void* p) {
    uint32_t a;
    asm("{ .reg .u64 t; cvta.to.shared.u64 t, %1; cvt.u32.u64 %0, t; }" : "=r"(a) : "l"(p));
    return a;
}

#define MBAR_INIT(a, c) \
    asm volatile("mbarrier.init.shared.b64 [%0], %1;" :: "r"(a), "r"(c) : "memory")
#define MBAR_EXPECT(a, b) \
    asm volatile("mbarrier.arrive.expect_tx.shared.b64 _, [%0], %1;" :: "r"(a), "r"(b) : "memory")
#define MBAR_ARRIVE(a) \
    asm volatile("mbarrier.arrive.shared.b64 _, [%0];" :: "r"(a) : "memory")

__device__ __forceinline__ void mbar_wait(uint32_t a, uint32_t par) {
    asm volatile(
        "{\n\t.reg .pred P;\n\t"
        "WL%=:\n\t"
        "mbarrier.try_wait.parity.acquire.cta.shared::cta.b64 P, [%0], %1, 0x989680;\n\t"
        "@P bra WD%=;\n\t"
        "bra WL%=;\n\t"
        "WD%=:\n\t}"
        :: "r"(a), "r"(par) : "memory");
}

__device__ __forceinline__ void tma2d(uint32_t dst, const CUtensorMap* m, int cx, int cy, uint32_t mbar) {
    asm volatile(
        "cp.async.bulk.tensor.2d.shared::cta.global.tile.mbarrier::complete_tx::bytes "
        "[%0], [%1, {%2, %3}], [%4];"
        :: "r"(dst), "l"(m), "r"(cx), "r"(cy), "r"(mbar) : "memory");
}

#define LDSM_X4(r0, r1, r2, r3, addr) \
    asm volatile("ldmatrix.sync.aligned.m8n8.x4.shared.b16 {%0,%1,%2,%3}, [%4];" \
        : "=r"(r0), "=r"(r1), "=r"(r2), "=r"(r3) : "r"(addr))

#define MMA16816(d, a, b0v, b1v) \
    asm volatile("mma.sync.aligned.m16n8k16.row.col.f32.f16.f16.f32 " \
        "{%0,%1,%2,%3}, {%4,%5,%6,%7}, {%8,%9}, {%0,%1,%2,%3};" \
        : "+f"((d)[0]), "+f"((d)[1]), "+f"((d)[2]), "+f"((d)[3]) \
        : "r"((a)[0]), "r"((a)[1]), "r"((a)[2]), "r"((a)[3]), "r"(b0v), "r"(b1v))

// ----------------------------- small kernels -------------------------------
__global__ void init_kernel() {
    if (threadIdx.x < NE) g_cnt[threadIdx.x] = 0;
}

__global__ void router_kernel(const float* __restrict__ x,
                              const float* __restrict__ sw,
                              const float* __restrict__ sb,
                              float* __restrict__ out_pmax) {
    int warp = threadIdx.x >> 5;
    int lane = threadIdx.x & 31;
    int t = blockIdx.x * 8 + warp;
    if (t >= T_TOK) return;

    const float* xp = x + (size_t)t * DM;
    float acc[NE];
#pragma unroll
    for (int e = 0; e < NE; e++) acc[e] = 0.f;
#pragma unroll 4
    for (int j = 0; j < DM / 32; j++) {
        int idx = lane + 32 * j;
        float xv = xp[idx];
#pragma unroll
        for (int e = 0; e < NE; e++) acc[e] += xv * sw[e * DM + idx];
    }
#pragma unroll
    for (int o = 16; o > 0; o >>= 1)
#pragma unroll
        for (int e = 0; e < NE; e++)
            acc[e] += __shfl_xor_sync(0xffffffffu, acc[e], o);

    if (lane == 0) {
        float l[NE], m = -1e30f;
#pragma unroll
        for (int e = 0; e < NE; e++) { l[e] = acc[e] + sb[e]; m = fmaxf(m, l[e]); }
        float p[NE], s = 0.f;
#pragma unroll
        for (int e = 0; e < NE; e++) { p[e] = expf(l[e] - m); s += p[e]; }
        float inv = 1.f / s;
        int best = 0; float bp = p[0];
#pragma unroll
        for (int e = 1; e < NE; e++) if (p[e] > bp) { bp = p[e]; best = e; }
#pragma unroll
        for (int e = 0; e < NE; e++) g_probs[t * NE + e] = p[e] * inv;
        out_pmax[t] = bp * inv;
        g_routes[t] = best;
        atomicAdd(&g_cnt[best], 1);
    }
}

__global__ void finalize_kernel(float* __restrict__ out) {
    int tid = threadIdx.x, warp = tid >> 5, lane = tid & 31;
    if (warp < NE) {
        float sum = 0.f;
        for (int t = lane; t < T_TOK; t += 32) sum += g_probs[t * NE + warp];
#pragma unroll
        for (int o = 16; o > 0; o >>= 1) sum += __shfl_xor_sync(0xffffffffu, sum, o);
        if (lane == 0) out[OFF_PSUM + warp] = sum;
    }
    if (tid == 0) {
        int off = 0, ns = 0;
        for (int e = 0; e < NE; e++) {
            int c = g_cnt[e];
            g_off[e] = off; g_fill[e] = 0;
            out[OFF_CNT + e] = (float)c;
            for (int i = 0; i < c; i += BM) {
                g_slot_e[ns] = e; g_slot_row0[ns] = off + i;
                g_slot_nv[ns] = min(BM, c - i); ns++;
            }
            off += c;
        }
        g_nslots = ns;
        out[OFF_ZERO] = 0.f;
    }
}

__global__ void scatter_kernel() {
    int t = blockIdx.x * blockDim.x + threadIdx.x;
    if (t < T_TOK) {
        int e = g_routes[t];
        int pos = g_off[e] + atomicAdd(&g_fill[e], 1);
        g_perm[pos] = t;
    }
}

// fp32 -> (fp16 hi, fp16 lo) split
__device__ __forceinline__ void split1h(float v, unsigned short& h, unsigned short& l) {
    __half hb = __float2half_rn(v);
    __half lb = __float2half_rn(v - __half2float(hb));
    h = __half_as_ushort(hb);
    l = __half_as_ushort(lb);
}

// weights: plain fp32 -> fp16 cast (B side is single precision product)
__global__ void convert_cast_kernel(const float4* __restrict__ src,
                                    uint2* __restrict__ dst, int n4) {
    int i = blockIdx.x * blockDim.x + threadIdx.x;
    if (i >= n4) return;
    float4 v = src[i];
    __half2 p0 = __floats2half2_rn(v.x, v.y);
    __half2 p1 = __floats2half2_rn(v.z, v.w);
    dst[i] = make_uint2(*(uint32_t*)&p0, *(uint32_t*)&p1);
}

__global__ void gather_x_kernel(const float* __restrict__ x) {
    int r = blockIdx.x;
    int t = threadIdx.x;               // 256 threads, 4 floats each
    int tok = g_perm[r];
    float4 v = ((const float4*)(x + (size_t)tok * DM))[t];
    unsigned short h0, l0, h1, l1, h2, l2, h3, l3;
    split1h(v.x, h0, l0); split1h(v.y, h1, l1); split1h(v.z, h2, l2); split1h(v.w, h3, l3);
    ((uint2*)g_Xhi)[(size_t)r * (DM / 4) + t] =
        make_uint2((uint32_t)h0 | ((uint32_t)h1 << 16), (uint32_t)h2 | ((uint32_t)h3 << 16));
    ((uint2*)g_Xlo)[(size_t)r * (DM / 4) + t] =
        make_uint2((uint32_t)l0 | ((uint32_t)l1 << 16), (uint32_t)l2 | ((uint32_t)l3 << 16));
}

// ----------------------------- GEMM building blocks ------------------------
// Producer: one thread streams all k-blocks through the 4-stage ring.
__device__ __forceinline__ void produce_all(
    uint32_t sb,
    const CUtensorMap* mAh, const CUtensorMap* mAl, const CUtensorMap* mBh,
    int rowA, int rowB, int nkb)
{
    uint32_t FULL = sb + BAR_OFF, EMPTY = sb + BAR_OFF + 32;
    for (int L = 0; L < nkb; L++) {
        int s = L & (STAGES - 1);
        if (L >= STAGES) mbar_wait(EMPTY + 8 * s, ((L / STAGES) - 1) & 1);
        uint32_t stg = sb + s * STG;
        uint32_t fb = FULL + 8 * s;
        MBAR_EXPECT(fb, STG);
        tma2d(stg,               mAh, L * BKE, rowA, fb);
        tma2d(stg + A_BYTES,     mAl, L * BKE, rowA, fb);
        tma2d(stg + 2 * A_BYTES, mBh, L * BKE, rowB, fb);
    }
}

// Consumer: 8 warps, warp tile 64x64 (mw in {0,1}, nw in {0..3}).
// SW64 swizzle: byte c within a 64B row, addr = row*64 + (c ^ (((row>>1)&3)<<4)).
// 2 products: Ahi*B and Alo*B. B fragments double-buffered across jp.
__device__ __forceinline__ void consume_all(
    uint32_t sb, int nkb, int lane, int mw, int nw,
    float (&acc)[4][8][4])
{
    int arow_l = (lane & 7) + ((lane >> 3) & 1) * 8;
    uint32_t acolsel = (uint32_t)((lane >> 4) * 16);
    uint32_t apat = (uint32_t)(((arow_l >> 1) & 3) << 4);
    uint32_t aoff[4];
#pragma unroll
    for (int i = 0; i < 4; i++) aoff[i] = (uint32_t)((mw * 64 + i * 16 + arow_l) * 64);

    int brow_l = ((lane >> 4) & 1) * 8 + (lane & 7);
    uint32_t bcolsel = (uint32_t)(((lane >> 3) & 1) * 16);
    uint32_t bpat = (uint32_t)(((brow_l >> 1) & 3) << 4);
    uint32_t boff[4];
#pragma unroll
    for (int jp = 0; jp < 4; jp++) boff[jp] = (uint32_t)((nw * 64 + jp * 16 + brow_l) * 64);

    uint32_t FULL = sb + BAR_OFF, EMPTY = sb + BAR_OFF + 32;

    for (int kb = 0; kb < nkb; kb++) {
        int s = kb & (STAGES - 1);
        mbar_wait(FULL + 8 * s, (kb / STAGES) & 1);
        uint32_t stg = sb + s * STG;
#pragma unroll
        for (int st = 0; st < 2; st++) {
            uint32_t kbyte = (uint32_t)(st * 32);
            uint32_t axor = (kbyte + acolsel) ^ apat;
            uint32_t bxor = (kbyte + bcolsel) ^ bpat;
            uint32_t ah[4][4], al[4][4];
#pragma unroll
            for (int i = 0; i < 4; i++) {
                uint32_t ad = stg + aoff[i] + axor;
                LDSM_X4(ah[i][0], ah[i][1], ah[i][2], ah[i][3], ad);
                LDSM_X4(al[i][0], al[i][1], al[i][2], al[i][3], ad + A_BYTES);
            }
            // double-buffered B fragments (single precision level)
            uint32_t bh[2][4];
            {
                uint32_t bd0 = stg + 2 * A_BYTES + boff[0] + bxor;
                LDSM_X4(bh[0][0], bh[0][1], bh[0][2], bh[0][3], bd0);
            }
#pragma unroll
            for (int jp = 0; jp < 4; jp++) {
                int cur = jp & 1;
                int nxt = cur ^ 1;
                if (jp < 3) {
                    uint32_t bdn = stg + 2 * A_BYTES + boff[jp + 1] + bxor;
                    LDSM_X4(bh[nxt][0], bh[nxt][1], bh[nxt][2], bh[nxt][3], bdn);
                }
                // product-major: same acc reused only every 8 MMAs
#pragma unroll
                for (int i = 0; i < 4; i++) {
                    MMA16816(acc[i][2 * jp],     ah[i], bh[cur][0], bh[cur][1]);
                    MMA16816(acc[i][2 * jp + 1], ah[i], bh[cur][2], bh[cur][3]);
                }
#pragma unroll
                for (int i = 0; i < 4; i++) {
                    MMA16816(acc[i][2 * jp],     al[i], bh[cur][0], bh[cur][1]);
                    MMA16816(acc[i][2 * jp + 1], al[i], bh[cur][2], bh[cur][3]);
                }
            }
        }
        if (lane == 0) MBAR_ARRIVE(EMPTY + 8 * s);
    }
}

// ----------------------------- GEMM kernels --------------------------------
// GEMM1: H[row, nb..nb+255] = relu(Xg @ w1[e]^T + b1[e]); store fp16 hi/lo.
__global__ __launch_bounds__(288, 1)
void gemm1_tc(const __grid_constant__ CUtensorMap mAh,
              const __grid_constant__ CUtensorMap mAl,
              const __grid_constant__ CUtensorMap mBh,
              const float* __restrict__ bias)
{
    int slot = blockIdx.y;
    if (slot >= g_nslots) return;
    int e = g_slot_e[slot], row0 = g_slot_row0[slot], nv = g_slot_nv[slot];
    int nb = blockIdx.x * BN;

    extern __shared__ __align__(1024) uint8_t smem_buf[];
    uint32_t sb = s2u(smem_buf);
    int tid = threadIdx.x, lane = tid & 31, warp = tid >> 5;

    if (tid == 0) {
        for (int s = 0; s < STAGES; s++) {
            MBAR_INIT(sb + BAR_OFF + 8 * s, 1);
            MBAR_INIT(sb + BAR_OFF + 32 + 8 * s, 8);
        }
    }
    asm volatile("fence.proxy.async.shared::cta;" ::: "memory");
    __syncthreads();   // all 9 warps participate, THEN roles diverge

    if (warp == 8) {
        if (lane == 0)
            produce_all(sb, &mAh, &mAl, &mBh, row0, e * DF + nb, DM / BKE);
        return;
    }

    float acc[4][8][4];
#pragma unroll
    for (int i = 0; i < 4; i++)
#pragma unroll
        for (int j = 0; j < 8; j++)
#pragma unroll
            for (int q = 0; q < 4; q++) acc[i][j][q] = 0.f;

    int mw = warp & 1, nw = warp >> 1;
    consume_all(sb, DM / BKE, lane, mw, nw, acc);

    // epilogue: bias + relu + fp16 hi/lo split store
    int rb = mw * 64 + (lane >> 2);
    int cbase = nb + nw * 64 + 2 * (lane & 3);
    const float* bb = bias + (size_t)e * DF;
#pragma unroll
    for (int i = 0; i < 4; i++) {
#pragma unroll
        for (int half = 0; half < 2; half++) {
            int r = rb + i * 16 + half * 8;
            if (r < nv) {
                size_t rowg = (size_t)(row0 + r);
#pragma unroll
                for (int j = 0; j < 8; j++) {
                    int colg = cbase + j * 8;
                    float2 bv = *(const float2*)(bb + colg);
                    float v0 = acc[i][j][2 * half]     + bv.x;
                    float v1 = acc[i][j][2 * half + 1] + bv.y;
                    v0 = fmaxf(v0, 0.f);
                    v1 = fmaxf(v1, 0.f);
                    unsigned short h0, l0, h1, l1;
                    split1h(v0, h0, l0); split1h(v1, h1, l1);
                    *(uint32_t*)(g_Hhi + rowg * DF + colg) = (uint32_t)h0 | ((uint32_t)h1 << 16);
                    *(uint32_t*)(g_Hlo + rowg * DF + colg) = (uint32_t)l0 | ((uint32_t)l1 << 16);
                }
            }
        }
    }
}

// GEMM2: out[tok, nb..nb+255] = H @ w2[e]^T + b2[e]  (scatter to d_out)
__global__ __launch_bounds__(288, 1)
void gemm2_tc(const __grid_constant__ CUtensorMap mAh,
              const __grid_constant__ CUtensorMap mAl,
              const __grid_constant__ CUtensorMap mBh,
              const float* __restrict__ bias,
              float* __restrict__ out)
{
    int slot = blockIdx.y;
    if (slot >= g_nslots) return;
    int e = g_slot_e[slot], row0 = g_slot_row0[slot], nv = g_slot_nv[slot];
    int nb = blockIdx.x * BN;

    extern __shared__ __align__(1024) uint8_t smem_buf[];
    uint32_t sb = s2u(smem_buf);
    int tid = threadIdx.x, lane = tid & 31, warp = tid >> 5;
    int* toks = (int*)(smem_buf + TOKS_OFF);

    if (tid == 0) {
        for (int s = 0; s < STAGES; s++) {
            MBAR_INIT(sb + BAR_OFF + 8 * s, 1);
            MBAR_INIT(sb + BAR_OFF + 32 + 8 * s, 8);
        }
    }
    if (tid < BM) toks[tid] = g_perm[row0 + min(tid, nv - 1)];
    asm volatile("fence.proxy.async.shared::cta;" ::: "memory");
    __syncthreads();   // all 9 warps participate, THEN roles diverge

    if (warp == 8) {
        if (lane == 0)
            produce_all(sb, &mAh, &mAl, &mBh, row0, e * DM + nb, DF / BKE);
        return;
    }

    float acc[4][8][4];
#pragma unroll
    for (int i = 0; i < 4; i++)
#pragma unroll
        for (int j = 0; j < 8; j++)
#pragma unroll
            for (int q = 0; q < 4; q++) acc[i][j][q] = 0.f;

    int mw = warp & 1, nw = warp >> 1;
    consume_all(sb, DF / BKE, lane, mw, nw, acc);

    // epilogue: bias + scatter fp32 store
    int rb = mw * 64 + (lane >> 2);
    int cbase = nb + nw * 64 + 2 * (lane & 3);
    const float* bb = bias + (size_t)e * DM;
#pragma unroll
    for (int i = 0; i < 4; i++) {
#pragma unroll
        for (int half = 0; half < 2; half++) {
            int r = rb + i * 16 + half * 8;
            if (r < nv) {
                int tok = toks[r];
                float* op = out + (size_t)tok * DM;
#pragma unroll
                for (int j = 0; j < 8; j++) {
                    int colg = cbase + j * 8;
                    float2 bv = *(const float2*)(bb + colg);
                    float2 v;
                    v.x = acc[i][j][2 * half]     + bv.x;
                    v.y = acc[i][j][2 * half + 1] + bv.y;
                    *(float2*)(op + colg) = v;
                }
            }
        }
    }
}

// ------------------------------- host side ---------------------------------
typedef CUresult (CUDAAPI *PFN_encodeTiled)(
    CUtensorMap*, CUtensorMapDataType, cuuint32_t, void*,
    const cuuint64_t*, const cuuint64_t*, const cuuint32_t*, const cuuint32_t*,
    CUtensorMapInterleave, CUtensorMapSwizzle, CUtensorMapL2promotion, CUtensorMapFloatOOBfill);

static PFN_encodeTiled get_encode_fn() {
    static PFN_encodeTiled fn = nullptr;
    if (!fn) {
        void* p = nullptr;
        cudaDriverEntryPointQueryResult st;
#if CUDART_VERSION >= 12050
        cudaGetDriverEntryPointByVersion("cuTensorMapEncodeTiled", &p, 12000, cudaEnableDefault, &st);
#else
        cudaGetDriverEntryPoint("cuTensorMapEncodeTiled", &p, cudaEnableDefault, &st);
#endif
        fn = (PFN_encodeTiled)p;
    }
    return fn;
}

// 2D fp16 map, SW64, box {32, box_rows}
static void make_map_2d(CUtensorMap* m, void* ptr, uint64_t d0, uint64_t d1, uint32_t box_rows) {
    cuuint64_t gd[2] = {d0, d1};
    cuuint64_t gs[1] = {d0 * 2};
    cuuint32_t box[2] = {BKE, box_rows};
    cuuint32_t es[2] = {1, 1};
    get_encode_fn()(m, CU_TENSOR_MAP_DATA_TYPE_FLOAT16, 2, ptr, gd, gs, box, es,
                    CU_TENSOR_MAP_INTERLEAVE_NONE, CU_TENSOR_MAP_SWIZZLE_64B,
                    CU_TENSOR_MAP_L2_PROMOTION_L2_128B, CU_TENSOR_MAP_FLOAT_OOB_FILL_NONE);
}

extern "C" void kernel_launch(void* const* d_in, const int* in_sizes, int n_in,
                              void* d_out, int out_size) {
    const float* x  = (const float*)d_in[0];
    const float* sw = (const float*)d_in[1];
    const float* sb = (const float*)d_in[2];
    const float* w1 = (const float*)d_in[3];
    const float* b1 = (const float*)d_in[4];
    const float* w2 = (const float*)d_in[5];
    const float* b2 = (const float*)d_in[6];
    float* out = (float*)d_out;

    void *p_xhi, *p_xlo, *p_w1h, *p_w2h, *p_hhi, *p_hlo;
    cudaGetSymbolAddress(&p_xhi, g_Xhi);  cudaGetSymbolAddress(&p_xlo, g_Xlo);
    cudaGetSymbolAddress(&p_w1h, g_w1h);  cudaGetSymbolAddress(&p_w2h, g_w2h);
    cudaGetSymbolAddress(&p_hhi, g_Hhi);  cudaGetSymbolAddress(&p_hlo, g_Hlo);

    CUtensorMap mXh, mXl, mW1h, mW2h, mHh, mHl;
    make_map_2d(&mXh,  p_xhi, DM, T_TOK, 128);
    make_map_2d(&mXl,  p_xlo, DM, T_TOK, 128);
    make_map_2d(&mW1h, p_w1h, DM, (uint64_t)NE * DF, 256);
    make_map_2d(&mW2h, p_w2h, DF, (uint64_t)NE * DM, 256);
    make_map_2d(&mHh,  p_hhi, DF, T_TOK, 128);
    make_map_2d(&mHl,  p_hlo, DF, T_TOK, 128);

    cudaFuncSetAttribute(gemm1_tc, cudaFuncAttributeMaxDynamicSharedMemorySize, SMEM_TOTAL);
    cudaFuncSetAttribute(gemm2_tc, cudaFuncAttributeMaxDynamicSharedMemorySize, SMEM_TOTAL);

    {
        int n4 = NE * DF * DM / 4;
        convert_cast_kernel<<<n4 / 256, 256>>>((const float4*)w1, (uint2*)p_w1h, n4);
        convert_cast_kernel<<<n4 / 256, 256>>>((const float4*)w2, (uint2*)p_w2h, n4);
    }

    init_kernel<<<1, 32>>>();
    router_kernel<<<T_TOK / 8, 256>>>(x, sw, sb, out + OFF_PMAX);
    finalize_kernel<<<1, 256>>>(out);
    scatter_kernel<<<T_TOK / 256, 256>>>();
    gather_x_kernel<<<T_TOK, 256>>>(x);

    gemm1_tc<<<dim3(DF / BN, 71), 288, SMEM_TOTAL>>>(mXh, mXl, mW1h, b1);
    gemm2_tc<<<dim3(DM / BN, 71), 288, SMEM_TOTAL>>>(mHh, mHl, mW2h, b2, out);
}

// round 10
// speedup vs baseline: 6.4353x; 1.5383x over previous
#include <cuda_runtime.h>
#include <cuda_fp16.h>
#include <cuda.h>
#include <cstdint>

// ---------------------------------------------------------------------------
// SwitchFeedForward top-1 MoE FFN. T=8192, d_model=1024, d_ff=4096, E=8.
// Round 9: pure single-product fp16 GEMMs (X, W1, H, W2 all single fp16,
// fp32 accum). HMMA count halved vs round 8 (validated linear scaling).
// 6-stage TMA pipeline, 24KB/stage. Predicted rel_err ~4-6e-4 (deterministic
// inputs, fixed seed).
// ---------------------------------------------------------------------------

#define T_TOK   8192
#define DM      1024
#define DF      4096
#define NE      8

#define OFF_CNT   (T_TOK * DM)
#define OFF_PSUM  (OFF_CNT + NE)
#define OFF_ZERO  (OFF_PSUM + NE)
#define OFF_PMAX  (OFF_ZERO + 1)

#define BM 128
#define BN 256
#define BKE 32                 // k elems per block (64 bytes per row, SW64)
#define MAX_SLOTS 80

#define A_BYTES   8192         // 128 rows * 64B
#define B_BYTES   16384        // 256 rows * 64B
#define STG       24576        // A + B
#define STAGES    6
#define BAR_OFF   (STAGES * STG)          // 147456
#define TOKS_OFF  (BAR_OFF + 128)
#define SMEM_TOTAL (TOKS_OFF + 512)       // ~148KB -> 1 CTA/SM

// ----------------------------- device scratch ------------------------------
__device__ __half g_Xh[(size_t)T_TOK * DM];
__device__ __half g_w1h[(size_t)NE * DF * DM];
__device__ __half g_w2h[(size_t)NE * DM * DF];
__device__ __half g_Hh[(size_t)T_TOK * DF];

__device__ float g_probs[T_TOK * NE];
__device__ int   g_routes[T_TOK];
__device__ int   g_cnt[NE];
__device__ int   g_off[NE];
__device__ int   g_fill[NE];
__device__ int   g_perm[T_TOK];
__device__ int   g_slot_e[MAX_SLOTS];
__device__ int   g_slot_row0[MAX_SLOTS];
__device__ int   g_slot_nv[MAX_SLOTS];
__device__ int   g_nslots;

// ----------------------------- PTX helpers ---------------------------------
__device__ __forceinline__ uint32_t s2u(const void* p) {
    uint32_t a;
    asm("{ .reg .u64 t; cvta.to.shared.u64 t, %1; cvt.u32.u64 %0, t; }" : "=r"(a) : "l"(p));
    return a;
}

#define MBAR_INIT(a, c) \
    asm volatile("mbarrier.init.shared.b64 [%0], %1;" :: "r"(a), "r"(c) : "memory")
#define MBAR_EXPECT(a, b) \
    asm volatile("mbarrier.arrive.expect_tx.shared.b64 _, [%0], %1;" :: "r"(a), "r"(b) : "memory")
#define MBAR_ARRIVE(a) \
    asm volatile("mbarrier.arrive.shared.b64 _, [%0];" :: "r"(a) : "memory")

__device__ __forceinline__ void mbar_wait(uint32_t a, uint32_t par) {
    asm volatile(
        "{\n\t.reg .pred P;\n\t"
        "WL%=:\n\t"
        "mbarrier.try_wait.parity.acquire.cta.shared::cta.b64 P, [%0], %1, 0x989680;\n\t"
        "@P bra WD%=;\n\t"
        "bra WL%=;\n\t"
        "WD%=:\n\t}"
        :: "r"(a), "r"(par) : "memory");
}

__device__ __forceinline__ void tma2d(uint32_t dst, const CUtensorMap* m, int cx, int cy, uint32_t mbar) {
    asm volatile(
        "cp.async.bulk.tensor.2d.shared::cta.global.tile.mbarrier::complete_tx::bytes "
        "[%0], [%1, {%2, %3}], [%4];"
        :: "r"(dst), "l"(m), "r"(cx), "r"(cy), "r"(mbar) : "memory");
}

#define LDSM_X4(r0, r1, r2, r3, addr) \
    asm volatile("ldmatrix.sync.aligned.m8n8.x4.shared.b16 {%0,%1,%2,%3}, [%4];" \
        : "=r"(r0), "=r"(r1), "=r"(r2), "=r"(r3) : "r"(addr))

#define MMA16816(d, a, b0v, b1v) \
    asm volatile("mma.sync.aligned.m16n8k16.row.col.f32.f16.f16.f32 " \
        "{%0,%1,%2,%3}, {%4,%5,%6,%7}, {%8,%9}, {%0,%1,%2,%3};" \
        : "+f"((d)[0]), "+f"((d)[1]), "+f"((d)[2]), "+f"((d)[3]) \
        : "r"((a)[0]), "r"((a)[1]), "r"((a)[2]), "r"((a)[3]), "r"(b0v), "r"(b1v))

// ----------------------------- small kernels -------------------------------
__global__ void init_kernel() {
    if (threadIdx.x < NE) g_cnt[threadIdx.x] = 0;
}

__global__ void router_kernel(const float* __restrict__ x,
                              const float* __restrict__ sw,
                              const float* __restrict__ sb,
                              float* __restrict__ out_pmax) {
    int warp = threadIdx.x >> 5;
    int lane = threadIdx.x & 31;
    int t = blockIdx.x * 8 + warp;
    if (t >= T_TOK) return;

    const float* xp = x + (size_t)t * DM;
    float acc[NE];
#pragma unroll
    for (int e = 0; e < NE; e++) acc[e] = 0.f;
#pragma unroll 4
    for (int j = 0; j < DM / 32; j++) {
        int idx = lane + 32 * j;
        float xv = xp[idx];
#pragma unroll
        for (int e = 0; e < NE; e++) acc[e] += xv * sw[e * DM + idx];
    }
#pragma unroll
    for (int o = 16; o > 0; o >>= 1)
#pragma unroll
        for (int e = 0; e < NE; e++)
            acc[e] += __shfl_xor_sync(0xffffffffu, acc[e], o);

    if (lane == 0) {
        float l[NE], m = -1e30f;
#pragma unroll
        for (int e = 0; e < NE; e++) { l[e] = acc[e] + sb[e]; m = fmaxf(m, l[e]); }
        float p[NE], s = 0.f;
#pragma unroll
        for (int e = 0; e < NE; e++) { p[e] = expf(l[e] - m); s += p[e]; }
        float inv = 1.f / s;
        int best = 0; float bp = p[0];
#pragma unroll
        for (int e = 1; e < NE; e++) if (p[e] > bp) { bp = p[e]; best = e; }
#pragma unroll
        for (int e = 0; e < NE; e++) g_probs[t * NE + e] = p[e] * inv;
        out_pmax[t] = bp * inv;
        g_routes[t] = best;
        atomicAdd(&g_cnt[best], 1);
    }
}

__global__ void finalize_kernel(float* __restrict__ out) {
    int tid = threadIdx.x, warp = tid >> 5, lane = tid & 31;
    if (warp < NE) {
        float sum = 0.f;
        for (int t = lane; t < T_TOK; t += 32) sum += g_probs[t * NE + warp];
#pragma unroll
        for (int o = 16; o > 0; o >>= 1) sum += __shfl_xor_sync(0xffffffffu, sum, o);
        if (lane == 0) out[OFF_PSUM + warp] = sum;
    }
    if (tid == 0) {
        int off = 0, ns = 0;
        for (int e = 0; e < NE; e++) {
            int c = g_cnt[e];
            g_off[e] = off; g_fill[e] = 0;
            out[OFF_CNT + e] = (float)c;
            for (int i = 0; i < c; i += BM) {
                g_slot_e[ns] = e; g_slot_row0[ns] = off + i;
                g_slot_nv[ns] = min(BM, c - i); ns++;
            }
            off += c;
        }
        g_nslots = ns;
        out[OFF_ZERO] = 0.f;
    }
}

__global__ void scatter_kernel() {
    int t = blockIdx.x * blockDim.x + threadIdx.x;
    if (t < T_TOK) {
        int e = g_routes[t];
        int pos = g_off[e] + atomicAdd(&g_fill[e], 1);
        g_perm[pos] = t;
    }
}

// weights: plain fp32 -> fp16 cast
__global__ void convert_cast_kernel(const float4* __restrict__ src,
                                    uint2* __restrict__ dst, int n4) {
    int i = blockIdx.x * blockDim.x + threadIdx.x;
    if (i >= n4) return;
    float4 v = src[i];
    __half2 p0 = __floats2half2_rn(v.x, v.y);
    __half2 p1 = __floats2half2_rn(v.z, v.w);
    dst[i] = make_uint2(*(uint32_t*)&p0, *(uint32_t*)&p1);
}

__global__ void gather_x_kernel(const float* __restrict__ x) {
    int r = blockIdx.x;
    int t = threadIdx.x;               // 256 threads, 4 floats each
    int tok = g_perm[r];
    float4 v = ((const float4*)(x + (size_t)tok * DM))[t];
    __half2 p0 = __floats2half2_rn(v.x, v.y);
    __half2 p1 = __floats2half2_rn(v.z, v.w);
    ((uint2*)g_Xh)[(size_t)r * (DM / 4) + t] = make_uint2(*(uint32_t*)&p0, *(uint32_t*)&p1);
}

// ----------------------------- GEMM building blocks ------------------------
// Producer: one thread streams all k-blocks through the 6-stage ring.
__device__ __forceinline__ void produce_all(
    uint32_t sb,
    const CUtensorMap* mA, const CUtensorMap* mB,
    int rowA, int rowB, int nkb)
{
    uint32_t FULL = sb + BAR_OFF, EMPTY = sb + BAR_OFF + 64;
    for (int L = 0; L < nkb; L++) {
        int s = L % STAGES;
        if (L >= STAGES) mbar_wait(EMPTY + 8 * s, ((L / STAGES) - 1) & 1);
        uint32_t stg = sb + s * STG;
        uint32_t fb = FULL + 8 * s;
        MBAR_EXPECT(fb, STG);
        tma2d(stg,           mA, L * BKE, rowA, fb);
        tma2d(stg + A_BYTES, mB, L * BKE, rowB, fb);
    }
}

// Consumer: 8 warps, warp tile 64x64 (mw in {0,1}, nw in {0..3}).
// SW64 swizzle: byte c within a 64B row, addr = row*64 + (c ^ (((row>>1)&3)<<4)).
// Single fp16 product; B fragments double-buffered across jp.
__device__ __forceinline__ void consume_all(
    uint32_t sb, int nkb, int lane, int mw, int nw,
    float (&acc)[4][8][4])
{
    int arow_l = (lane & 7) + ((lane >> 3) & 1) * 8;
    uint32_t acolsel = (uint32_t)((lane >> 4) * 16);
    uint32_t apat = (uint32_t)(((arow_l >> 1) & 3) << 4);
    uint32_t aoff[4];
#pragma unroll
    for (int i = 0; i < 4; i++) aoff[i] = (uint32_t)((mw * 64 + i * 16 + arow_l) * 64);

    int brow_l = ((lane >> 4) & 1) * 8 + (lane & 7);
    uint32_t bcolsel = (uint32_t)(((lane >> 3) & 1) * 16);
    uint32_t bpat = (uint32_t)(((brow_l >> 1) & 3) << 4);
    uint32_t boff[4];
#pragma unroll
    for (int jp = 0; jp < 4; jp++) boff[jp] = (uint32_t)((nw * 64 + jp * 16 + brow_l) * 64);

    uint32_t FULL = sb + BAR_OFF, EMPTY = sb + BAR_OFF + 64;

    for (int kb = 0; kb < nkb; kb++) {
        int s = kb % STAGES;
        mbar_wait(FULL + 8 * s, (kb / STAGES) & 1);
        uint32_t stg = sb + s * STG;
#pragma unroll
        for (int st = 0; st < 2; st++) {
            uint32_t kbyte = (uint32_t)(st * 32);
            uint32_t axor = (kbyte + acolsel) ^ apat;
            uint32_t bxor = (kbyte + bcolsel) ^ bpat;
            uint32_t ah[4][4];
#pragma unroll
            for (int i = 0; i < 4; i++) {
                uint32_t ad = stg + aoff[i] + axor;
                LDSM_X4(ah[i][0], ah[i][1], ah[i][2], ah[i][3], ad);
            }
            // double-buffered B fragments
            uint32_t bh[2][4];
            {
                uint32_t bd0 = stg + A_BYTES + boff[0] + bxor;
                LDSM_X4(bh[0][0], bh[0][1], bh[0][2], bh[0][3], bd0);
            }
#pragma unroll
            for (int jp = 0; jp < 4; jp++) {
                int cur = jp & 1;
                int nxt = cur ^ 1;
                if (jp < 3) {
                    uint32_t bdn = stg + A_BYTES + boff[jp + 1] + bxor;
                    LDSM_X4(bh[nxt][0], bh[nxt][1], bh[nxt][2], bh[nxt][3], bdn);
                }
#pragma unroll
                for (int i = 0; i < 4; i++) {
                    MMA16816(acc[i][2 * jp],     ah[i], bh[cur][0], bh[cur][1]);
                    MMA16816(acc[i][2 * jp + 1], ah[i], bh[cur][2], bh[cur][3]);
                }
            }
        }
        if (lane == 0) MBAR_ARRIVE(EMPTY + 8 * s);
    }
}

// ----------------------------- GEMM kernels --------------------------------
// GEMM1: H[row, nb..nb+255] = relu(Xg @ w1[e]^T + b1[e]); store fp16.
__global__ __launch_bounds__(288, 1)
void gemm1_tc(const __grid_constant__ CUtensorMap mA,
              const __grid_constant__ CUtensorMap mB,
              const float* __restrict__ bias)
{
    int slot = blockIdx.y;
    if (slot >= g_nslots) return;
    int e = g_slot_e[slot], row0 = g_slot_row0[slot], nv = g_slot_nv[slot];
    int nb = blockIdx.x * BN;

    extern __shared__ __align__(1024) uint8_t smem_buf[];
    uint32_t sb = s2u(smem_buf);
    int tid = threadIdx.x, lane = tid & 31, warp = tid >> 5;

    if (tid == 0) {
        for (int s = 0; s < STAGES; s++) {
            MBAR_INIT(sb + BAR_OFF + 8 * s, 1);
            MBAR_INIT(sb + BAR_OFF + 64 + 8 * s, 8);
        }
    }
    asm volatile("fence.proxy.async.shared::cta;" ::: "memory");
    __syncthreads();   // all 9 warps participate, THEN roles diverge

    if (warp == 8) {
        if (lane == 0)
            produce_all(sb, &mA, &mB, row0, e * DF + nb, DM / BKE);
        return;
    }

    float acc[4][8][4];
#pragma unroll
    for (int i = 0; i < 4; i++)
#pragma unroll
        for (int j = 0; j < 8; j++)
#pragma unroll
            for (int q = 0; q < 4; q++) acc[i][j][q] = 0.f;

    int mw = warp & 1, nw = warp >> 1;
    consume_all(sb, DM / BKE, lane, mw, nw, acc);

    // epilogue: bias + relu + fp16 store
    int rb = mw * 64 + (lane >> 2);
    int cbase = nb + nw * 64 + 2 * (lane & 3);
    const float* bb = bias + (size_t)e * DF;
#pragma unroll
    for (int i = 0; i < 4; i++) {
#pragma unroll
        for (int half = 0; half < 2; half++) {
            int r = rb + i * 16 + half * 8;
            if (r < nv) {
                size_t rowg = (size_t)(row0 + r);
#pragma unroll
                for (int j = 0; j < 8; j++) {
                    int colg = cbase + j * 8;
                    float2 bv = *(const float2*)(bb + colg);
                    float v0 = fmaxf(acc[i][j][2 * half]     + bv.x, 0.f);
                    float v1 = fmaxf(acc[i][j][2 * half + 1] + bv.y, 0.f);
                    __half2 hp = __floats2half2_rn(v0, v1);
                    *(uint32_t*)(g_Hh + rowg * DF + colg) = *(uint32_t*)&hp;
                }
            }
        }
    }
}

// GEMM2: out[tok, nb..nb+255] = H @ w2[e]^T + b2[e]  (scatter to d_out)
__global__ __launch_bounds__(288, 1)
void gemm2_tc(const __grid_constant__ CUtensorMap mA,
              const __grid_constant__ CUtensorMap mB,
              const float* __restrict__ bias,
              float* __restrict__ out)
{
    int slot = blockIdx.y;
    if (slot >= g_nslots) return;
    int e = g_slot_e[slot], row0 = g_slot_row0[slot], nv = g_slot_nv[slot];
    int nb = blockIdx.x * BN;

    extern __shared__ __align__(1024) uint8_t smem_buf[];
    uint32_t sb = s2u(smem_buf);
    int tid = threadIdx.x, lane = tid & 31, warp = tid >> 5;
    int* toks = (int*)(smem_buf + TOKS_OFF);

    if (tid == 0) {
        for (int s = 0; s < STAGES; s++) {
            MBAR_INIT(sb + BAR_OFF + 8 * s, 1);
            MBAR_INIT(sb + BAR_OFF + 64 + 8 * s, 8);
        }
    }
    if (tid < BM) toks[tid] = g_perm[row0 + min(tid, nv - 1)];
    asm volatile("fence.proxy.async.shared::cta;" ::: "memory");
    __syncthreads();   // all 9 warps participate, THEN roles diverge

    if (warp == 8) {
        if (lane == 0)
            produce_all(sb, &mA, &mB, row0, e * DM + nb, DF / BKE);
        return;
    }

    float acc[4][8][4];
#pragma unroll
    for (int i = 0; i < 4; i++)
#pragma unroll
        for (int j = 0; j < 8; j++)
#pragma unroll
            for (int q = 0; q < 4; q++) acc[i][j][q] = 0.f;

    int mw = warp & 1, nw = warp >> 1;
    consume_all(sb, DF / BKE, lane, mw, nw, acc);

    // epilogue: bias + scatter fp32 store
    int rb = mw * 64 + (lane >> 2);
    int cbase = nb + nw * 64 + 2 * (lane & 3);
    const float* bb = bias + (size_t)e * DM;
#pragma unroll
    for (int i = 0; i < 4; i++) {
#pragma unroll
        for (int half = 0; half < 2; half++) {
            int r = rb + i * 16 + half * 8;
            if (r < nv) {
                int tok = toks[r];
                float* op = out + (size_t)tok * DM;
#pragma unroll
                for (int j = 0; j < 8; j++) {
                    int colg = cbase + j * 8;
                    float2 bv = *(const float2*)(bb + colg);
                    float2 v;
                    v.x = acc[i][j][2 * half]     + bv.x;
                    v.y = acc[i][j][2 * half + 1] + bv.y;
                    *(float2*)(op + colg) = v;
                }
            }
        }
    }
}

// ------------------------------- host side ---------------------------------
typedef CUresult (CUDAAPI *PFN_encodeTiled)(
    CUtensorMap*, CUtensorMapDataType, cuuint32_t, void*,
    const cuuint64_t*, const cuuint64_t*, const cuuint32_t*, const cuuint32_t*,
    CUtensorMapInterleave, CUtensorMapSwizzle, CUtensorMapL2promotion, CUtensorMapFloatOOBfill);

static PFN_encodeTiled get_encode_fn() {
    static PFN_encodeTiled fn = nullptr;
    if (!fn) {
        void* p = nullptr;
        cudaDriverEntryPointQueryResult st;
#if CUDART_VERSION >= 12050
        cudaGetDriverEntryPointByVersion("cuTensorMapEncodeTiled", &p, 12000, cudaEnableDefault, &st);
#else
        cudaGetDriverEntryPoint("cuTensorMapEncodeTiled", &p, cudaEnableDefault, &st);
#endif
        fn = (PFN_encodeTiled)p;
    }
    return fn;
}

// 2D fp16 map, SW64, box {32, box_rows}
static void make_map_2d(CUtensorMap* m, void* ptr, uint64_t d0, uint64_t d1, uint32_t box_rows) {
    cuuint64_t gd[2] = {d0, d1};
    cuuint64_t gs[1] = {d0 * 2};
    cuuint32_t box[2] = {BKE, box_rows};
    cuuint32_t es[2] = {1, 1};
    get_encode_fn()(m, CU_TENSOR_MAP_DATA_TYPE_FLOAT16, 2, ptr, gd, gs, box, es,
                    CU_TENSOR_MAP_INTERLEAVE_NONE, CU_TENSOR_MAP_SWIZZLE_64B,
                    CU_TENSOR_MAP_L2_PROMOTION_L2_128B, CU_TENSOR_MAP_FLOAT_OOB_FILL_NONE);
}

extern "C" void kernel_launch(void* const* d_in, const int* in_sizes, int n_in,
                              void* d_out, int out_size) {
    const float* x  = (const float*)d_in[0];
    const float* sw = (const float*)d_in[1];
    const float* sb = (const float*)d_in[2];
    const float* w1 = (const float*)d_in[3];
    const float* b1 = (const float*)d_in[4];
    const float* w2 = (const float*)d_in[5];
    const float* b2 = (const float*)d_in[6];
    float* out = (float*)d_out;

    void *p_xh, *p_w1h, *p_w2h, *p_hh;
    cudaGetSymbolAddress(&p_xh, g_Xh);
    cudaGetSymbolAddress(&p_w1h, g_w1h);
    cudaGetSymbolAddress(&p_w2h, g_w2h);
    cudaGetSymbolAddress(&p_hh, g_Hh);

    CUtensorMap mXh, mW1h, mW2h, mHh;
    make_map_2d(&mXh,  p_xh,  DM, T_TOK, 128);
    make_map_2d(&mW1h, p_w1h, DM, (uint64_t)NE * DF, 256);
    make_map_2d(&mW2h, p_w2h, DF, (uint64_t)NE * DM, 256);
    make_map_2d(&mHh,  p_hh,  DF, T_TOK, 128);

    cudaFuncSetAttribute(gemm1_tc, cudaFuncAttributeMaxDynamicSharedMemorySize, SMEM_TOTAL);
    cudaFuncSetAttribute(gemm2_tc, cudaFuncAttributeMaxDynamicSharedMemorySize, SMEM_TOTAL);

    {
        int n4 = NE * DF * DM / 4;
        convert_cast_kernel<<<n4 / 256, 256>>>((const float4*)w1, (uint2*)p_w1h, n4);
        convert_cast_kernel<<<n4 / 256, 256>>>((const float4*)w2, (uint2*)p_w2h, n4);
    }

    init_kernel<<<1, 32>>>();
    router_kernel<<<T_TOK / 8, 256>>>(x, sw, sb, out + OFF_PMAX);
    finalize_kernel<<<1, 256>>>(out);
    scatter_kernel<<<T_TOK / 256, 256>>>();
    gather_x_kernel<<<T_TOK, 256>>>(x);

    gemm1_tc<<<dim3(DF / BN, 71), 288, SMEM_TOTAL>>>(mXh, mW1h, b1);
    gemm2_tc<<<dim3(DM / BN, 71), 288, SMEM_TOTAL>>>(mHh, mW2h, b2, out);
}

// round 11
// speedup vs baseline: 6.6297x; 1.0302x over previous
#include <cuda_runtime.h>
#include <cuda_fp16.h>
#include <cuda.h>
#include <cstdint>

// ---------------------------------------------------------------------------
// SwitchFeedForward top-1 MoE FFN. T=8192, d_model=1024, d_ff=4096, E=8.
// Round 10: single-product fp16 GEMMs (validated: 563us, 4.15e-4), now with
// 2 CTAs/SM for cross-CTA bubble hiding: BM=128 BN=128, 160 threads
// (4 consumer warps 64x64 + 1 producer), 6-stage 16KB ring, ~99KB smem/CTA.
// launch_bounds(160,2) -> 204 regs/thread cap, no spills (~180 needed).
// ---------------------------------------------------------------------------

#define T_TOK   8192
#define DM      1024
#define DF      4096
#define NE      8

#define OFF_CNT   (T_TOK * DM)
#define OFF_PSUM  (OFF_CNT + NE)
#define OFF_ZERO  (OFF_PSUM + NE)
#define OFF_PMAX  (OFF_ZERO + 1)

#define BM 128
#define BN 128
#define BKE 32                 // k elems per block (64 bytes per row, SW64)
#define MAX_SLOTS 80

#define A_BYTES   8192         // 128 rows * 64B
#define B_BYTES   8192         // 128 rows * 64B
#define STG       16384        // A + B
#define STAGES    6
#define BAR_OFF   (STAGES * STG)          // 98304
#define TOKS_OFF  (BAR_OFF + 128)
#define SMEM_TOTAL (TOKS_OFF + 512)       // 98944 -> 2 CTAs/SM

// ----------------------------- device scratch ------------------------------
__device__ __half g_Xh[(size_t)T_TOK * DM];
__device__ __half g_w1h[(size_t)NE * DF * DM];
__device__ __half g_w2h[(size_t)NE * DM * DF];
__device__ __half g_Hh[(size_t)T_TOK * DF];

__device__ float g_probs[T_TOK * NE];
__device__ int   g_routes[T_TOK];
__device__ int   g_cnt[NE];
__device__ int   g_off[NE];
__device__ int   g_fill[NE];
__device__ int   g_perm[T_TOK];
__device__ int   g_slot_e[MAX_SLOTS];
__device__ int   g_slot_row0[MAX_SLOTS];
__device__ int   g_slot_nv[MAX_SLOTS];
__device__ int   g_nslots;

// ----------------------------- PTX helpers ---------------------------------
__device__ __forceinline__ uint32_t s2u(const void* p) {
    uint32_t a;
    asm("{ .reg .u64 t; cvta.to.shared.u64 t, %1; cvt.u32.u64 %0, t; }" : "=r"(a) : "l"(p));
    return a;
}

#define MBAR_INIT(a, c) \
    asm volatile("mbarrier.init.shared.b64 [%0], %1;" :: "r"(a), "r"(c) : "memory")
#define MBAR_EXPECT(a, b) \
    asm volatile("mbarrier.arrive.expect_tx.shared.b64 _, [%0], %1;" :: "r"(a), "r"(b) : "memory")
#define MBAR_ARRIVE(a) \
    asm volatile("mbarrier.arrive.shared.b64 _, [%0];" :: "r"(a) : "memory")

__device__ __forceinline__ void mbar_wait(uint32_t a, uint32_t par) {
    asm volatile(
        "{\n\t.reg .pred P;\n\t"
        "WL%=:\n\t"
        "mbarrier.try_wait.parity.acquire.cta.shared::cta.b64 P, [%0], %1, 0x989680;\n\t"
        "@P bra WD%=;\n\t"
        "bra WL%=;\n\t"
        "WD%=:\n\t}"
        :: "r"(a), "r"(par) : "memory");
}

__device__ __forceinline__ void tma2d(uint32_t dst, const CUtensorMap* m, int cx, int cy, uint32_t mbar) {
    asm volatile(
        "cp.async.bulk.tensor.2d.shared::cta.global.tile.mbarrier::complete_tx::bytes "
        "[%0], [%1, {%2, %3}], [%4];"
        :: "r"(dst), "l"(m), "r"(cx), "r"(cy), "r"(mbar) : "memory");
}

#define LDSM_X4(r0, r1, r2, r3, addr) \
    asm volatile("ldmatrix.sync.aligned.m8n8.x4.shared.b16 {%0,%1,%2,%3}, [%4];" \
        : "=r"(r0), "=r"(r1), "=r"(r2), "=r"(r3) : "r"(addr))

#define MMA16816(d, a, b0v, b1v) \
    asm volatile("mma.sync.aligned.m16n8k16.row.col.f32.f16.f16.f32 " \
        "{%0,%1,%2,%3}, {%4,%5,%6,%7}, {%8,%9}, {%0,%1,%2,%3};" \
        : "+f"((d)[0]), "+f"((d)[1]), "+f"((d)[2]), "+f"((d)[3]) \
        : "r"((a)[0]), "r"((a)[1]), "r"((a)[2]), "r"((a)[3]), "r"(b0v), "r"(b1v))

// ----------------------------- small kernels -------------------------------
__global__ void init_kernel() {
    if (threadIdx.x < NE) g_cnt[threadIdx.x] = 0;
}

__global__ void router_kernel(const float* __restrict__ x,
                              const float* __restrict__ sw,
                              const float* __restrict__ sb,
                              float* __restrict__ out_pmax) {
    int warp = threadIdx.x >> 5;
    int lane = threadIdx.x & 31;
    int t = blockIdx.x * 8 + warp;
    if (t >= T_TOK) return;

    const float* xp = x + (size_t)t * DM;
    float acc[NE];
#pragma unroll
    for (int e = 0; e < NE; e++) acc[e] = 0.f;
#pragma unroll 4
    for (int j = 0; j < DM / 32; j++) {
        int idx = lane + 32 * j;
        float xv = xp[idx];
#pragma unroll
        for (int e = 0; e < NE; e++) acc[e] += xv * sw[e * DM + idx];
    }
#pragma unroll
    for (int o = 16; o > 0; o >>= 1)
#pragma unroll
        for (int e = 0; e < NE; e++)
            acc[e] += __shfl_xor_sync(0xffffffffu, acc[e], o);

    if (lane == 0) {
        float l[NE], m = -1e30f;
#pragma unroll
        for (int e = 0; e < NE; e++) { l[e] = acc[e] + sb[e]; m = fmaxf(m, l[e]); }
        float p[NE], s = 0.f;
#pragma unroll
        for (int e = 0; e < NE; e++) { p[e] = expf(l[e] - m); s += p[e]; }
        float inv = 1.f / s;
        int best = 0; float bp = p[0];
#pragma unroll
        for (int e = 1; e < NE; e++) if (p[e] > bp) { bp = p[e]; best = e; }
#pragma unroll
        for (int e = 0; e < NE; e++) g_probs[t * NE + e] = p[e] * inv;
        out_pmax[t] = bp * inv;
        g_routes[t] = best;
        atomicAdd(&g_cnt[best], 1);
    }
}

__global__ void finalize_kernel(float* __restrict__ out) {
    int tid = threadIdx.x, warp = tid >> 5, lane = tid & 31;
    if (warp < NE) {
        float sum = 0.f;
        for (int t = lane; t < T_TOK; t += 32) sum += g_probs[t * NE + warp];
#pragma unroll
        for (int o = 16; o > 0; o >>= 1) sum += __shfl_xor_sync(0xffffffffu, sum, o);
        if (lane == 0) out[OFF_PSUM + warp] = sum;
    }
    if (tid == 0) {
        int off = 0, ns = 0;
        for (int e = 0; e < NE; e++) {
            int c = g_cnt[e];
            g_off[e] = off; g_fill[e] = 0;
            out[OFF_CNT + e] = (float)c;
            for (int i = 0; i < c; i += BM) {
                g_slot_e[ns] = e; g_slot_row0[ns] = off + i;
                g_slot_nv[ns] = min(BM, c - i); ns++;
            }
            off += c;
        }
        g_nslots = ns;
        out[OFF_ZERO] = 0.f;
    }
}

__global__ void scatter_kernel() {
    int t = blockIdx.x * blockDim.x + threadIdx.x;
    if (t < T_TOK) {
        int e = g_routes[t];
        int pos = g_off[e] + atomicAdd(&g_fill[e], 1);
        g_perm[pos] = t;
    }
}

// weights: plain fp32 -> fp16 cast
__global__ void convert_cast_kernel(const float4* __restrict__ src,
                                    uint2* __restrict__ dst, int n4) {
    int i = blockIdx.x * blockDim.x + threadIdx.x;
    if (i >= n4) return;
    float4 v = src[i];
    __half2 p0 = __floats2half2_rn(v.x, v.y);
    __half2 p1 = __floats2half2_rn(v.z, v.w);
    dst[i] = make_uint2(*(uint32_t*)&p0, *(uint32_t*)&p1);
}

__global__ void gather_x_kernel(const float* __restrict__ x) {
    int r = blockIdx.x;
    int t = threadIdx.x;               // 256 threads, 4 floats each
    int tok = g_perm[r];
    float4 v = ((const float4*)(x + (size_t)tok * DM))[t];
    __half2 p0 = __floats2half2_rn(v.x, v.y);
    __half2 p1 = __floats2half2_rn(v.z, v.w);
    ((uint2*)g_Xh)[(size_t)r * (DM / 4) + t] = make_uint2(*(uint32_t*)&p0, *(uint32_t*)&p1);
}

// ----------------------------- GEMM building blocks ------------------------
// Producer: one thread streams all k-blocks through the 6-stage ring.
__device__ __forceinline__ void produce_all(
    uint32_t sb,
    const CUtensorMap* mA, const CUtensorMap* mB,
    int rowA, int rowB, int nkb)
{
    uint32_t FULL = sb + BAR_OFF, EMPTY = sb + BAR_OFF + 64;
    for (int L = 0; L < nkb; L++) {
        int s = L % STAGES;
        if (L >= STAGES) mbar_wait(EMPTY + 8 * s, ((L / STAGES) - 1) & 1);
        uint32_t stg = sb + s * STG;
        uint32_t fb = FULL + 8 * s;
        MBAR_EXPECT(fb, STG);
        tma2d(stg,           mA, L * BKE, rowA, fb);
        tma2d(stg + A_BYTES, mB, L * BKE, rowB, fb);
    }
}

// Consumer: 4 warps, warp tile 64x64 (mw in {0,1}, nw in {0,1}).
// SW64 swizzle: byte c within a 64B row, addr = row*64 + (c ^ (((row>>1)&3)<<4)).
// Single fp16 product; B fragments double-buffered across jp.
__device__ __forceinline__ void consume_all(
    uint32_t sb, int nkb, int lane, int mw, int nw,
    float (&acc)[4][8][4])
{
    int arow_l = (lane & 7) + ((lane >> 3) & 1) * 8;
    uint32_t acolsel = (uint32_t)((lane >> 4) * 16);
    uint32_t apat = (uint32_t)(((arow_l >> 1) & 3) << 4);
    uint32_t aoff[4];
#pragma unroll
    for (int i = 0; i < 4; i++) aoff[i] = (uint32_t)((mw * 64 + i * 16 + arow_l) * 64);

    int brow_l = ((lane >> 4) & 1) * 8 + (lane & 7);
    uint32_t bcolsel = (uint32_t)(((lane >> 3) & 1) * 16);
    uint32_t bpat = (uint32_t)(((brow_l >> 1) & 3) << 4);
    uint32_t boff[4];
#pragma unroll
    for (int jp = 0; jp < 4; jp++) boff[jp] = (uint32_t)((nw * 64 + jp * 16 + brow_l) * 64);

    uint32_t FULL = sb + BAR_OFF, EMPTY = sb + BAR_OFF + 64;

    for (int kb = 0; kb < nkb; kb++) {
        int s = kb % STAGES;
        mbar_wait(FULL + 8 * s, (kb / STAGES) & 1);
        uint32_t stg = sb + s * STG;
#pragma unroll
        for (int st = 0; st < 2; st++) {
            uint32_t kbyte = (uint32_t)(st * 32);
            uint32_t axor = (kbyte + acolsel) ^ apat;
            uint32_t bxor = (kbyte + bcolsel) ^ bpat;
            uint32_t ah[4][4];
#pragma unroll
            for (int i = 0; i < 4; i++) {
                uint32_t ad = stg + aoff[i] + axor;
                LDSM_X4(ah[i][0], ah[i][1], ah[i][2], ah[i][3], ad);
            }
            // double-buffered B fragments
            uint32_t bh[2][4];
            {
                uint32_t bd0 = stg + A_BYTES + boff[0] + bxor;
                LDSM_X4(bh[0][0], bh[0][1], bh[0][2], bh[0][3], bd0);
            }
#pragma unroll
            for (int jp = 0; jp < 4; jp++) {
                int cur = jp & 1;
                int nxt = cur ^ 1;
                if (jp < 3) {
                    uint32_t bdn = stg + A_BYTES + boff[jp + 1] + bxor;
                    LDSM_X4(bh[nxt][0], bh[nxt][1], bh[nxt][2], bh[nxt][3], bdn);
                }
#pragma unroll
                for (int i = 0; i < 4; i++) {
                    MMA16816(acc[i][2 * jp],     ah[i], bh[cur][0], bh[cur][1]);
                    MMA16816(acc[i][2 * jp + 1], ah[i], bh[cur][2], bh[cur][3]);
                }
            }
        }
        if (lane == 0) MBAR_ARRIVE(EMPTY + 8 * s);
    }
}

// ----------------------------- GEMM kernels --------------------------------
// GEMM1: H[row, nb..nb+127] = relu(Xg @ w1[e]^T + b1[e]); store fp16.
__global__ __launch_bounds__(160, 2)
void gemm1_tc(const __grid_constant__ CUtensorMap mA,
              const __grid_constant__ CUtensorMap mB,
              const float* __restrict__ bias)
{
    int slot = blockIdx.y;
    if (slot >= g_nslots) return;
    int e = g_slot_e[slot], row0 = g_slot_row0[slot], nv = g_slot_nv[slot];
    int nb = blockIdx.x * BN;

    extern __shared__ __align__(1024) uint8_t smem_buf[];
    uint32_t sb = s2u(smem_buf);
    int tid = threadIdx.x, lane = tid & 31, warp = tid >> 5;

    if (tid == 0) {
        for (int s = 0; s < STAGES; s++) {
            MBAR_INIT(sb + BAR_OFF + 8 * s, 1);
            MBAR_INIT(sb + BAR_OFF + 64 + 8 * s, 4);
        }
    }
    asm volatile("fence.proxy.async.shared::cta;" ::: "memory");
    __syncthreads();   // all 5 warps participate, THEN roles diverge

    if (warp == 4) {
        if (lane == 0)
            produce_all(sb, &mA, &mB, row0, e * DF + nb, DM / BKE);
        return;
    }

    float acc[4][8][4];
#pragma unroll
    for (int i = 0; i < 4; i++)
#pragma unroll
        for (int j = 0; j < 8; j++)
#pragma unroll
            for (int q = 0; q < 4; q++) acc[i][j][q] = 0.f;

    int mw = warp & 1, nw = warp >> 1;
    consume_all(sb, DM / BKE, lane, mw, nw, acc);

    // epilogue: bias + relu + fp16 store
    int rb = mw * 64 + (lane >> 2);
    int cbase = nb + nw * 64 + 2 * (lane & 3);
    const float* bb = bias + (size_t)e * DF;
#pragma unroll
    for (int i = 0; i < 4; i++) {
#pragma unroll
        for (int half = 0; half < 2; half++) {
            int r = rb + i * 16 + half * 8;
            if (r < nv) {
                size_t rowg = (size_t)(row0 + r);
#pragma unroll
                for (int j = 0; j < 8; j++) {
                    int colg = cbase + j * 8;
                    float2 bv = *(const float2*)(bb + colg);
                    float v0 = fmaxf(acc[i][j][2 * half]     + bv.x, 0.f);
                    float v1 = fmaxf(acc[i][j][2 * half + 1] + bv.y, 0.f);
                    __half2 hp = __floats2half2_rn(v0, v1);
                    *(uint32_t*)(g_Hh + rowg * DF + colg) = *(uint32_t*)&hp;
                }
            }
        }
    }
}

// GEMM2: out[tok, nb..nb+127] = H @ w2[e]^T + b2[e]  (scatter to d_out)
__global__ __launch_bounds__(160, 2)
void gemm2_tc(const __grid_constant__ CUtensorMap mA,
              const __grid_constant__ CUtensorMap mB,
              const float* __restrict__ bias,
              float* __restrict__ out)
{
    int slot = blockIdx.y;
    if (slot >= g_nslots) return;
    int e = g_slot_e[slot], row0 = g_slot_row0[slot], nv = g_slot_nv[slot];
    int nb = blockIdx.x * BN;

    extern __shared__ __align__(1024) uint8_t smem_buf[];
    uint32_t sb = s2u(smem_buf);
    int tid = threadIdx.x, lane = tid & 31, warp = tid >> 5;
    int* toks = (int*)(smem_buf + TOKS_OFF);

    if (tid == 0) {
        for (int s = 0; s < STAGES; s++) {
            MBAR_INIT(sb + BAR_OFF + 8 * s, 1);
            MBAR_INIT(sb + BAR_OFF + 64 + 8 * s, 4);
        }
    }
    if (tid < BM) toks[tid] = g_perm[row0 + min(tid, nv - 1)];
    asm volatile("fence.proxy.async.shared::cta;" ::: "memory");
    __syncthreads();   // all 5 warps participate, THEN roles diverge

    if (warp == 4) {
        if (lane == 0)
            produce_all(sb, &mA, &mB, row0, e * DM + nb, DF / BKE);
        return;
    }

    float acc[4][8][4];
#pragma unroll
    for (int i = 0; i < 4; i++)
#pragma unroll
        for (int j = 0; j < 8; j++)
#pragma unroll
            for (int q = 0; q < 4; q++) acc[i][j][q] = 0.f;

    int mw = warp & 1, nw = warp >> 1;
    consume_all(sb, DF / BKE, lane, mw, nw, acc);

    // epilogue: bias + scatter fp32 store
    int rb = mw * 64 + (lane >> 2);
    int cbase = nb + nw * 64 + 2 * (lane & 3);
    const float* bb = bias + (size_t)e * DM;
#pragma unroll
    for (int i = 0; i < 4; i++) {
#pragma unroll
        for (int half = 0; half < 2; half++) {
            int r = rb + i * 16 + half * 8;
            if (r < nv) {
                int tok = toks[r];
                float* op = out + (size_t)tok * DM;
#pragma unroll
                for (int j = 0; j < 8; j++) {
                    int colg = cbase + j * 8;
                    float2 bv = *(const float2*)(bb + colg);
                    float2 v;
                    v.x = acc[i][j][2 * half]     + bv.x;
                    v.y = acc[i][j][2 * half + 1] + bv.y;
                    *(float2*)(op + colg) = v;
                }
            }
        }
    }
}

// ------------------------------- host side ---------------------------------
typedef CUresult (CUDAAPI *PFN_encodeTiled)(
    CUtensorMap*, CUtensorMapDataType, cuuint32_t, void*,
    const cuuint64_t*, const cuuint64_t*, const cuuint32_t*, const cuuint32_t*,
    CUtensorMapInterleave, CUtensorMapSwizzle, CUtensorMapL2promotion, CUtensorMapFloatOOBfill);

static PFN_encodeTiled get_encode_fn() {
    static PFN_encodeTiled fn = nullptr;
    if (!fn) {
        void* p = nullptr;
        cudaDriverEntryPointQueryResult st;
#if CUDART_VERSION >= 12050
        cudaGetDriverEntryPointByVersion("cuTensorMapEncodeTiled", &p, 12000, cudaEnableDefault, &st);
#else
        cudaGetDriverEntryPoint("cuTensorMapEncodeTiled", &p, cudaEnableDefault, &st);
#endif
        fn = (PFN_encodeTiled)p;
    }
    return fn;
}

// 2D fp16 map, SW64, box {32, box_rows}
static void make_map_2d(CUtensorMap* m, void* ptr, uint64_t d0, uint64_t d1, uint32_t box_rows) {
    cuuint64_t gd[2] = {d0, d1};
    cuuint64_t gs[1] = {d0 * 2};
    cuuint32_t box[2] = {BKE, box_rows};
    cuuint32_t es[2] = {1, 1};
    get_encode_fn()(m, CU_TENSOR_MAP_DATA_TYPE_FLOAT16, 2, ptr, gd, gs, box, es,
                    CU_TENSOR_MAP_INTERLEAVE_NONE, CU_TENSOR_MAP_SWIZZLE_64B,
                    CU_TENSOR_MAP_L2_PROMOTION_L2_128B, CU_TENSOR_MAP_FLOAT_OOB_FILL_NONE);
}

extern "C" void kernel_launch(void* const* d_in, const int* in_sizes, int n_in,
                              void* d_out, int out_size) {
    const float* x  = (const float*)d_in[0];
    const float* sw = (const float*)d_in[1];
    const float* sb = (const float*)d_in[2];
    const float* w1 = (const float*)d_in[3];
    const float* b1 = (const float*)d_in[4];
    const float* w2 = (const float*)d_in[5];
    const float* b2 = (const float*)d_in[6];
    float* out = (float*)d_out;

    void *p_xh, *p_w1h, *p_w2h, *p_hh;
    cudaGetSymbolAddress(&p_xh, g_Xh);
    cudaGetSymbolAddress(&p_w1h, g_w1h);
    cudaGetSymbolAddress(&p_w2h, g_w2h);
    cudaGetSymbolAddress(&p_hh, g_Hh);

    CUtensorMap mXh, mW1h, mW2h, mHh;
    make_map_2d(&mXh,  p_xh,  DM, T_TOK, 128);
    make_map_2d(&mW1h, p_w1h, DM, (uint64_t)NE * DF, 128);
    make_map_2d(&mW2h, p_w2h, DF, (uint64_t)NE * DM, 128);
    make_map_2d(&mHh,  p_hh,  DF, T_TOK, 128);

    cudaFuncSetAttribute(gemm1_tc, cudaFuncAttributeMaxDynamicSharedMemorySize, SMEM_TOTAL);
    cudaFuncSetAttribute(gemm2_tc, cudaFuncAttributeMaxDynamicSharedMemorySize, SMEM_TOTAL);

    {
        int n4 = NE * DF * DM / 4;
        convert_cast_kernel<<<n4 / 256, 256>>>((const float4*)w1, (uint2*)p_w1h, n4);
        convert_cast_kernel<<<n4 / 256, 256>>>((const float4*)w2, (uint2*)p_w2h, n4);
    }

    init_kernel<<<1, 32>>>();
    router_kernel<<<T_TOK / 8, 256>>>(x, sw, sb, out + OFF_PMAX);
    finalize_kernel<<<1, 256>>>(out);
    scatter_kernel<<<T_TOK / 256, 256>>>();
    gather_x_kernel<<<T_TOK, 256>>>(x);

    gemm1_tc<<<dim3(DF / BN, 71), 160, SMEM_TOTAL>>>(mXh, mW1h, b1);
    gemm2_tc<<<dim3(DM / BN, 71), 160, SMEM_TOTAL>>>(mHh, mW2h, b2, out);
}